// round 14
// baseline (speedup 1.0000x reference)
#include <cuda_runtime.h>
#include <cuda_bf16.h>
#include <cstdint>

// ---------------- problem constants ----------------
constexpr int   Bb   = 64;
constexpr int   Dd   = 1024;
constexpr int   Tt   = 512;
constexpr int   KC   = 8;
constexpr int   HH   = 16384;
constexpr int   LMAX = 1024;
constexpr int   NROW = Bb + Bb*KC;   // 576
constexpr float GAMMA_C   = 10.0f;
constexpr float EPS_POOL  = 1e-6f;
constexpr float EPS_NORM  = 1e-12f;

// output layout (floats)
constexpr size_t OFF_RECON_V = 0;
constexpr size_t OFF_VIEWS   = OFF_RECON_V + (size_t)Bb*KC*Dd;
constexpr size_t OFF_RECON_T = OFF_VIEWS   + (size_t)Bb*KC*Dd;
constexpr size_t OFF_TGLOBAL = OFF_RECON_T + (size_t)Bb*Dd;
constexpr size_t OFF_LAT_V   = OFF_TGLOBAL + (size_t)Bb*Dd;
constexpr size_t OFF_LAT_T   = OFF_LAT_V   + (size_t)Bb*KC*HH;
constexpr size_t OUT_TOTAL   = OFF_LAT_T   + (size_t)Bb*HH;

// ---------------- scratch ----------------
__device__ float g_acts[(size_t)NROW*HH];               // 36 MB
__device__ float g_m[(size_t)Bb*KC*LMAX];
__device__ float g_den[Bb*KC];
__device__ float g_tkv[NROW*32];
__device__ int   g_tki[NROW*32];
__device__ float g_wvT[(size_t)HH*Dd];                  // 64 MB transposed dec_v_w
__device__ __nv_bfloat16 g_apack[(size_t)640*3072];     // [hiX, loX, hiX] (xinv folded)
__device__ __nv_bfloat16 g_bt[(size_t)HH*2048];         // [hiW, loW] text (winv folded)
__device__ __nv_bfloat16 g_bv[(size_t)HH*2048];         // [hiW, loW] views (winv folded)

// ---------------- PTX helpers ----------------
__device__ __forceinline__ uint32_t smem_u32(const void* p){
    uint32_t a; asm("{ .reg .u64 t; cvta.to.shared.u64 t, %1; cvt.u32.u64 %0, t; }" : "=r"(a) : "l"(p));
    return a;
}
__device__ __forceinline__ void fma2(unsigned long long &c, unsigned long long a, unsigned long long b){
    asm("fma.rn.f32x2 %0, %1, %2, %0;" : "+l"(c) : "l"(a), "l"(b));
}
__device__ __forceinline__ unsigned long long dup2(float x){
    unsigned long long r; asm("mov.b64 %0, {%1, %1};" : "=l"(r) : "f"(x)); return r;
}
__device__ __forceinline__ float2 unpk(unsigned long long v){
    float2 r; asm("mov.b64 {%0, %1}, %2;" : "=f"(r.x), "=f"(r.y) : "l"(v)); return r;
}
__device__ __forceinline__ void cp_async16(uint32_t s, const void* g){
    asm volatile("cp.async.cg.shared.global [%0], [%1], 16;" :: "r"(s), "l"(g));
}
#define CP_COMMIT() asm volatile("cp.async.commit_group;" ::: "memory")
#define CP_WAIT1()  asm volatile("cp.async.wait_group 1;" ::: "memory")

__device__ __forceinline__ void ldm_x4(uint32_t* r, uint32_t addr){
    asm volatile("ldmatrix.sync.aligned.m8n8.x4.shared.b16 {%0,%1,%2,%3}, [%4];"
        : "=r"(r[0]), "=r"(r[1]), "=r"(r[2]), "=r"(r[3]) : "r"(addr));
}
__device__ __forceinline__ void mma16816(float* c, const uint32_t* a, const uint32_t* b){
    asm volatile("mma.sync.aligned.m16n8k16.row.col.f32.bf16.bf16.f32 "
        "{%0,%1,%2,%3}, {%4,%5,%6,%7}, {%8,%9}, {%0,%1,%2,%3};"
        : "+f"(c[0]), "+f"(c[1]), "+f"(c[2]), "+f"(c[3])
        : "r"(a[0]), "r"(a[1]), "r"(a[2]), "r"(a[3]), "r"(b[0]), "r"(b[1]));
}

// ---------------- 1. text global pooling ----------------
__global__ void k_tglobal(const float* __restrict__ t_pad, const float* __restrict__ t_mask,
                          float* __restrict__ out)
{
    int blk = blockIdx.x;               // 256 blocks = 64 b x 4 chunks
    int b = blk >> 2, ch = blk & 3;
    int tid = threadIdx.x;              // 256
    __shared__ float sm[Tt];
    __shared__ float s_inv;
    for (int t = tid; t < Tt; t += 256) sm[t] = t_mask[b*Tt + t];
    __syncthreads();
    if (tid == 0){
        float s = 0.f;
        for (int t = 0; t < Tt; t++) s += sm[t];
        s_inv = 1.f / (s + EPS_POOL);
    }
    __syncthreads();
    int d0 = ch*256 + tid;
    const float* tp = t_pad + (size_t)b*Tt*Dd + d0;
    float acc = 0.f;
    #pragma unroll 4
    for (int t = 0; t < Tt; t++) acc += tp[(size_t)t*Dd] * sm[t];
    out[OFF_TGLOBAL + (size_t)b*Dd + d0] = acc * s_inv;
}

// ---------------- 2. gaussian weights ----------------
__global__ void k_mden(const float* __restrict__ centers, const int* __restrict__ grid_thws)
{
    int b = blockIdx.x, tid = threadIdx.x;
    int Hg = grid_thws[1], Wg = grid_thws[2];
    int L  = Hg * Wg;
    __shared__ float partial[KC][8];
    int lane = tid & 31, warp = tid >> 5;
    for (int k = 0; k < KC; k++){
        float cx = centers[(b*KC+k)*2 + 0];
        float cy = centers[(b*KC+k)*2 + 1];
        float local = 0.f;
        for (int l = tid; l < L; l += 256){
            int iy = l / Wg, ix = l % Wg;
            float px = (ix + 0.5f) / (float)Wg;
            float py = (iy + 0.5f) / (float)Hg;
            float dx = cx - px, dy = cy - py;
            float m = expf(-GAMMA_C * (dx*dx + dy*dy));
            g_m[((size_t)b*KC + k)*LMAX + l] = m;
            local += m;
        }
        #pragma unroll
        for (int off = 16; off; off >>= 1) local += __shfl_down_sync(0xffffffffu, local, off);
        if (lane == 0) partial[k][warp] = local;
    }
    __syncthreads();
    if (tid < KC){
        float s = 0.f;
        #pragma unroll
        for (int w = 0; w < 8; w++) s += partial[tid][w];
        g_den[b*KC + tid] = s;
    }
}

// ---------------- 3. gaussian view pooling (f32x2) ----------------
__global__ void k_views(const float* __restrict__ v_pad, float* __restrict__ out)
{
    extern __shared__ unsigned long long ms2[];   // 64 KB
    int blk = blockIdx.x;
    int b = blk >> 2, ch = blk & 3;
    int tid = threadIdx.x;               // 128
    for (int i = tid; i < KC*LMAX; i += 128) ms2[i] = dup2(g_m[(size_t)b*KC*LMAX + i]);
    __syncthreads();

    int d0 = ch*256 + tid*2;
    const float* vp = v_pad + (size_t)b*LMAX*Dd + d0;
    unsigned long long acc[KC];
    #pragma unroll
    for (int k = 0; k < KC; k++) acc[k] = 0ull;

    for (int l = 0; l < LMAX; l++){
        unsigned long long v = *(const unsigned long long*)(vp + (size_t)l*Dd);
        #pragma unroll
        for (int k = 0; k < KC; k++) fma2(acc[k], ms2[k*LMAX + l], v);
    }
    #pragma unroll
    for (int k = 0; k < KC; k++){
        float inv = 1.f / (g_den[b*KC + k] + EPS_POOL);
        float2 a = unpk(acc[k]);
        float2 o = make_float2(a.x*inv, a.y*inv);
        *(float2*)(out + OFF_VIEWS + ((size_t)(b*KC + k))*Dd + d0) = o;
    }
}

// ---------------- 4. pack B (both enc matrices): warp-per-row, winv folded ----------------
__global__ void k_packb(const float* __restrict__ enc_t, const float* __restrict__ enc_v,
                        __nv_bfloat16* __restrict__ bt, __nv_bfloat16* __restrict__ bv)
{
    const float* enc = blockIdx.y ? enc_v : enc_t;
    __nv_bfloat16* Bp = blockIdx.y ? bv : bt;
    int warp = threadIdx.x >> 5, lane = threadIdx.x & 31;
    int n = blockIdx.x*8 + warp;

    const float4* src = (const float4*)(enc + (size_t)n*Dd);
    float4 v[8];
    float s = 0.f;
    #pragma unroll
    for (int i = 0; i < 8; i++){
        v[i] = src[i*32 + lane];
        s += v[i].x*v[i].x + v[i].y*v[i].y + v[i].z*v[i].z + v[i].w*v[i].w;
    }
    #pragma unroll
    for (int off = 16; off; off >>= 1) s += __shfl_xor_sync(0xffffffffu, s, off);
    float sc = 1.f / fmaxf(sqrtf(s), EPS_NORM);

    __nv_bfloat16* row = Bp + (size_t)n*2048;
    #pragma unroll
    for (int i = 0; i < 8; i++){
        float xs[4] = {v[i].x*sc, v[i].y*sc, v[i].z*sc, v[i].w*sc};
        union { __nv_bfloat16 b[4]; unsigned long long u; } uh, ul;
        #pragma unroll
        for (int j = 0; j < 4; j++){
            __nv_bfloat16 h = __float2bfloat16(xs[j]);
            uh.b[j] = h;
            ul.b[j] = __float2bfloat16(xs[j] - __bfloat162float(h));
        }
        int e = (i*32 + lane)*4;
        *(unsigned long long*)(row + e)        = uh.u;
        *(unsigned long long*)(row + 1024 + e) = ul.u;
    }
}

// ---------------- 5. pack A with fused row norm (rows 64..127 pad zeros) ----------------
__global__ void k_packa(const float* __restrict__ out, __nv_bfloat16* __restrict__ Ap)
{
    int r = blockIdx.x, tid = threadIdx.x;     // 640 blocks, 256 threads
    float4 v = make_float4(0.f, 0.f, 0.f, 0.f);
    if (r < 64)        v = ((const float4*)(out + OFF_TGLOBAL + (size_t)r*Dd))[tid];
    else if (r >= 128) v = ((const float4*)(out + OFF_VIEWS + (size_t)(r-128)*Dd))[tid];

    float s = v.x*v.x + v.y*v.y + v.z*v.z + v.w*v.w;
    __shared__ float ws[8];
    __shared__ float s_scale;
    int lane = tid & 31, warp = tid >> 5;
    #pragma unroll
    for (int off = 16; off; off >>= 1) s += __shfl_down_sync(0xffffffffu, s, off);
    if (lane == 0) ws[warp] = s;
    __syncthreads();
    if (tid == 0){
        float t = 0.f;
        #pragma unroll
        for (int w = 0; w < 8; w++) t += ws[w];
        s_scale = 1.f / fmaxf(sqrtf(t), EPS_NORM);
    }
    __syncthreads();
    float sc = s_scale;

    float xs[4] = {v.x*sc, v.y*sc, v.z*sc, v.w*sc};
    union { __nv_bfloat16 b[4]; unsigned long long u; } uh, ul;
    #pragma unroll
    for (int i = 0; i < 4; i++){
        __nv_bfloat16 h = __float2bfloat16(xs[i]);
        uh.b[i] = h;
        ul.b[i] = __float2bfloat16(xs[i] - __bfloat162float(h));
    }
    __nv_bfloat16* row = Ap + (size_t)r*3072;
    *(unsigned long long*)(row + tid*4)        = uh.u;
    *(unsigned long long*)(row + 1024 + tid*4) = ul.u;
    *(unsigned long long*)(row + 2048 + tid*4) = uh.u;
}

// ---------------- 6. merged bf16-split GEMM (text + views) ----------------
// grid (HH/128, 5): by=0 text (Mvalid=64), by=1..4 views (Mvalid=128).
// CTA tile 128x128, K=3072 in 48 chunks of 64; 3-stage cp.async, 2 CTAs/SM.
// LAUNCHED TWICE this round: second launch is idempotent; dur delta = T_gemm.
constexpr int STAGE_BYTES = 32768;                 // A 16KB + B 16KB
constexpr int GEMM_SMEM   = 1024 + 3*STAGE_BYTES;  // ~97 KB

__device__ __forceinline__ int b_off(int c){
    return (c < 32) ? ((c & 15) * 128) : (2048 + (c - 32) * 128);
}

__device__ __forceinline__ void load_chunk(const char* Ab, const char* Bbp,
                                           int aOff, int bOff,
                                           uint32_t smA, uint32_t smB, int tid)
{
    #pragma unroll
    for (int i = 0; i < 4; i++){            // A: 128 rows x 8 segs
        int idx = i*256 + tid;
        int row = idx >> 3, seg = idx & 7;
        uint32_t col = (uint32_t)(seg*16) ^ (uint32_t)((row & 7) << 4);
        cp_async16(smA + row*128 + col, Ab + (size_t)row*6144 + aOff + seg*16);
    }
    #pragma unroll
    for (int i = 0; i < 4; i++){            // B: 128 rows x 8 segs
        int idx = i*256 + tid;
        int row = idx >> 3, seg = idx & 7;
        uint32_t col = (uint32_t)(seg*16) ^ (uint32_t)((row & 7) << 4);
        cp_async16(smB + row*128 + col, Bbp + (size_t)row*4096 + bOff + seg*16);
    }
}

__global__ void __launch_bounds__(256, 2)
k_gemm_mma(const __nv_bfloat16* __restrict__ Apack,
           const __nv_bfloat16* __restrict__ Bt, const __nv_bfloat16* __restrict__ Bv,
           float* __restrict__ acts)
{
    extern __shared__ char dsm[];
    const int tid = threadIdx.x;
    const int by  = blockIdx.y;
    const int bn0 = blockIdx.x * 128;
    const int Mvalid = by ? 128 : 64;
    const __nv_bfloat16* Bpack = by ? Bv : Bt;
    float* actsBase = acts + (by ? (size_t)(64 + (by-1)*128)*HH : 0);

    uint32_t sb = (smem_u32(dsm) + 1023u) & ~1023u;
    const char* Ab  = (const char*)(Apack + (size_t)by*128*3072);
    const char* Bbp = (const char*)(Bpack + (size_t)bn0*2048);

    #pragma unroll
    for (int c = 0; c < 2; c++){
        uint32_t st = sb + c*STAGE_BYTES;
        load_chunk(Ab, Bbp, c*128, b_off(c), st, st + 16384, tid);
        CP_COMMIT();
    }

    const int w = tid >> 5, lane = tid & 31;
    const int wm = w & 3, wn = w >> 2;

    float acc[2][8][4];
    #pragma unroll
    for (int mt = 0; mt < 2; mt++)
        #pragma unroll
        for (int nt = 0; nt < 8; nt++)
            #pragma unroll
            for (int j = 0; j < 4; j++) acc[mt][nt][j] = 0.f;

    const int arow  = wm*32 + (lane & 15);
    const int acolh = (lane >> 4) * 16;
    const int brow  = wn*64 + (lane & 7) + ((lane >> 4) << 3);
    const int bcolh = ((lane >> 3) & 1) * 16;

    for (int c = 0; c < 48; c++){
        CP_WAIT1();
        __syncthreads();
        int nc = c + 2;
        if (nc < 48){
            uint32_t st = sb + (nc % 3)*STAGE_BYTES;
            load_chunk(Ab, Bbp, nc*128, b_off(nc), st, st + 16384, tid);
            CP_COMMIT();
        }
        int buf = c % 3;
        uint32_t stA = sb + buf*STAGE_BYTES;
        uint32_t stB = stA + 16384;
        #pragma unroll
        for (int ks = 0; ks < 4; ks++){
            int kb = ks*32;
            uint32_t af[2][4], bf[4][4];
            #pragma unroll
            for (int mt = 0; mt < 2; mt++){
                int r = arow + mt*16;
                uint32_t col = (uint32_t)(kb + acolh) ^ (uint32_t)((r & 7) << 4);
                ldm_x4(af[mt], stA + r*128 + col);
            }
            #pragma unroll
            for (int nt = 0; nt < 4; nt++){
                int r = brow + nt*16;
                uint32_t col = (uint32_t)(kb + bcolh) ^ (uint32_t)((r & 7) << 4);
                ldm_x4(bf[nt], stB + r*128 + col);
            }
            #pragma unroll
            for (int mt = 0; mt < 2; mt++)
                #pragma unroll
                for (int nt = 0; nt < 4; nt++){
                    mma16816(acc[mt][nt*2],   af[mt], bf[nt]);
                    mma16816(acc[mt][nt*2+1], af[mt], bf[nt] + 2);
                }
        }
    }

    const int r0 = lane >> 2;
    const int cb = (lane & 3) * 2;
    #pragma unroll
    for (int mt = 0; mt < 2; mt++){
        #pragma unroll
        for (int half = 0; half < 2; half++){
            int ml = wm*32 + mt*16 + half*8 + r0;
            if (ml < Mvalid){
                float* dst = actsBase + (size_t)ml*HH + bn0 + wn*64 + cb;
                #pragma unroll
                for (int nt = 0; nt < 8; nt++){
                    float v0 = acc[mt][nt][half*2 + 0];
                    float v1 = acc[mt][nt][half*2 + 1];
                    float c0 = fminf(1.f, fmaxf(-1.f, v0));
                    float c1 = fminf(1.f, fmaxf(-1.f, v1));
                    float2 o;
                    o.x = 2.f - sqrtf(fmaxf(0.f, 2.f - 2.f*c0));
                    o.y = 2.f - sqrtf(fmaxf(0.f, 2.f - 2.f*c1));
                    *(float2*)(dst + nt*8) = o;
                }
            }
        }
    }
}

// ---------------- 7. transpose dec_v_w [D,H] -> g_wvT [H,D] ----------------
__global__ void k_trans(const float* __restrict__ W, float* __restrict__ WT)
{
    __shared__ float t[32][33];
    int tx = threadIdx.x & 31, ty = threadIdx.x >> 5;   // 32 x 8
    int h0 = blockIdx.x * 32, d0 = blockIdx.y * 32;
    #pragma unroll
    for (int j = 0; j < 32; j += 8)
        t[ty+j][tx] = W[(size_t)(d0+ty+j)*HH + h0 + tx];
    __syncthreads();
    #pragma unroll
    for (int j = 0; j < 32; j += 8)
        WT[(size_t)(h0+ty+j)*Dd + d0 + tx] = t[tx][ty+j];
}

// ---------------- 8. top-32 per row: local top-6 + candidate select ----------------
__global__ void k_topk(const float* __restrict__ acts, float* __restrict__ out)
{
    extern __shared__ float sv[];   // 64 KB (fallback only)
    __shared__ unsigned long long red[8];
    __shared__ unsigned long long s_win;
    __shared__ float selv[32];
    __shared__ int   seli[32];

    int n = blockIdx.x, tid = threadIdx.x;    // 256 threads
    int lane = tid & 31, warp = tid >> 5;
    const float* row = acts + (size_t)n*HH;
    float* latrow = (n < Bb) ? out + OFF_LAT_T + (size_t)n*HH
                             : out + OFF_LAT_V + (size_t)(n-Bb)*HH;

    float4 z = make_float4(0.f, 0.f, 0.f, 0.f);
    for (int i = tid; i < HH/4; i += 256) ((float4*)latrow)[i] = z;

    unsigned long long loc[6] = {0ull,0ull,0ull,0ull,0ull,0ull};
    for (int i = tid; i < HH; i += 256){
        unsigned int bits = __float_as_uint(row[i]);
        unsigned long long pk = ((unsigned long long)bits << 32) | (unsigned int)(HH-1-i);
        if (pk > loc[5]){
            loc[5] = pk;
            #pragma unroll
            for (int j = 5; j > 0; j--){
                if (loc[j] > loc[j-1]){ unsigned long long t = loc[j]; loc[j] = loc[j-1]; loc[j-1] = t; }
            }
        }
    }
    const unsigned long long orig5 = loc[5];

    for (int p = 0; p < 32; p++){
        unsigned long long best = loc[0];
        #pragma unroll
        for (int j = 1; j < 6; j++) best = (loc[j] > best) ? loc[j] : best;
        #pragma unroll
        for (int off = 16; off; off >>= 1){
            unsigned long long o = __shfl_down_sync(0xffffffffu, best, off);
            best = (o > best) ? o : best;
        }
        if (lane == 0) red[warp] = best;
        __syncthreads();
        if (tid < 32){
            unsigned long long b2 = (tid < 8) ? red[tid] : 0ull;
            #pragma unroll
            for (int off = 4; off; off >>= 1){
                unsigned long long o = __shfl_down_sync(0xffffffffu, b2, off);
                b2 = (o > b2) ? o : b2;
            }
            if (tid == 0){
                s_win = b2;
                selv[p] = __uint_as_float((unsigned int)(b2 >> 32));
                seli[p] = HH - 1 - (int)(unsigned int)(b2 & 0xffffffffull);
            }
        }
        __syncthreads();
        unsigned long long wk = s_win;
        #pragma unroll
        for (int j = 0; j < 6; j++) if (loc[j] == wk) loc[j] = 0ull;
    }

    unsigned long long kth = s_win;
    int bad = (orig5 > kth) ? 1 : 0;
    if (__syncthreads_or(bad)){
        for (int i = tid; i < HH; i += 256) sv[i] = row[i];
        __syncthreads();
        for (int p = 0; p < 32; p++){
            unsigned long long best = 0ull;
            for (int i = tid; i < HH; i += 256){
                unsigned int bits = __float_as_uint(sv[i]);
                unsigned long long pk = ((unsigned long long)bits << 32) | (unsigned int)(HH-1-i);
                best = (pk > best) ? pk : best;
            }
            #pragma unroll
            for (int off = 16; off; off >>= 1){
                unsigned long long o = __shfl_down_sync(0xffffffffu, best, off);
                best = (o > best) ? o : best;
            }
            if (lane == 0) red[warp] = best;
            __syncthreads();
            if (tid < 32){
                unsigned long long b2 = (tid < 8) ? red[tid] : 0ull;
                #pragma unroll
                for (int off = 4; off; off >>= 1){
                    unsigned long long o = __shfl_down_sync(0xffffffffu, b2, off);
                    b2 = (o > b2) ? o : b2;
                }
                if (tid == 0){
                    int idx = HH - 1 - (int)(unsigned int)(b2 & 0xffffffffull);
                    selv[p] = __uint_as_float((unsigned int)(b2 >> 32));
                    seli[p] = idx;
                    sv[idx] = 0.0f;
                }
            }
            __syncthreads();
        }
    }

    if (tid < 32){
        float v = selv[tid]; int h = seli[tid];
        latrow[h] = v;
        g_tkv[n*32 + tid] = v;
        g_tki[n*32 + tid] = h;
    }
}

// ---------------- 9. sparse reconstruction ----------------
__global__ void k_recon(const float* __restrict__ dec_t_w, const float* __restrict__ dec_t_b,
                        const float* __restrict__ dec_v_b, const float* __restrict__ wvT,
                        float* __restrict__ out)
{
    int n = blockIdx.x, tid = threadIdx.x;
    __shared__ float vk[32];
    __shared__ int   hk[32];
    if (tid < 32){ vk[tid] = g_tkv[n*32+tid]; hk[tid] = g_tki[n*32+tid]; }
    __syncthreads();

    if (n < Bb){
        float* dst = out + OFF_RECON_T + (size_t)n*Dd;
        for (int d = tid; d < Dd; d += 256){
            float acc = dec_t_b[d];
            const float* wr = dec_t_w + (size_t)d*HH;
            #pragma unroll
            for (int k = 0; k < 32; k++) acc += vk[k] * wr[hk[k]];
            dst[d] = acc;
        }
    } else {
        float* dst = out + OFF_RECON_V + (size_t)(n-Bb)*Dd;
        float4 acc = ((const float4*)dec_v_b)[tid];
        #pragma unroll
        for (int k = 0; k < 32; k++){
            float4 wv = ((const float4*)(wvT + (size_t)hk[k]*Dd))[tid];
            float v = vk[k];
            acc.x += v*wv.x; acc.y += v*wv.y; acc.z += v*wv.z; acc.w += v*wv.w;
        }
        ((float4*)dst)[tid] = acc;
    }
}

// ---------------- launch ----------------
extern "C" void kernel_launch(void* const* d_in, const int* in_sizes, int n_in,
                              void* d_out, int out_size)
{
    const float* v_pad    = (const float*)d_in[0];
    const int*   grid_thws= (const int*)  d_in[2];
    const float* t_pad    = (const float*)d_in[3];
    const float* t_mask   = (const float*)d_in[4];
    const float* centers  = (const float*)d_in[5];
    const float* enc_v    = (const float*)d_in[6];
    const float* dec_v_w  = (const float*)d_in[7];
    const float* dec_v_b  = (const float*)d_in[8];
    const float* enc_t    = (const float*)d_in[9];
    const float* dec_t_w  = (const float*)d_in[10];
    const float* dec_t_b  = (const float*)d_in[11];
    float* out = (float*)d_out;

    float *p_acts, *p_wvT;
    __nv_bfloat16 *p_apack, *p_bt, *p_bv;
    cudaGetSymbolAddress((void**)&p_acts,  g_acts);
    cudaGetSymbolAddress((void**)&p_wvT,   g_wvT);
    cudaGetSymbolAddress((void**)&p_apack, g_apack);
    cudaGetSymbolAddress((void**)&p_bt,    g_bt);
    cudaGetSymbolAddress((void**)&p_bv,    g_bv);

    cudaFuncSetAttribute(k_views,    cudaFuncAttributeMaxDynamicSharedMemorySize, 65536);
    cudaFuncSetAttribute(k_gemm_mma, cudaFuncAttributeMaxDynamicSharedMemorySize, GEMM_SMEM);
    cudaFuncSetAttribute(k_topk,     cudaFuncAttributeMaxDynamicSharedMemorySize, 65536);

    k_tglobal<<<Bb*4, 256>>>(t_pad, t_mask, out);
    k_mden<<<Bb, 256>>>(centers, grid_thws);
    k_views<<<Bb*4, 128, 65536>>>(v_pad, out);
    k_packb<<<dim3(HH/8, 2), 256>>>(enc_t, enc_v, p_bt, p_bv);
    k_packa<<<640, 256>>>(out, p_apack);
    // MEASUREMENT: GEMM launched twice (idempotent). dur_us - 624 ≈ T_gemm.
    k_gemm_mma<<<dim3(HH/128, 5), 256, GEMM_SMEM>>>(p_apack, p_bt, p_bv, p_acts);
    k_gemm_mma<<<dim3(HH/128, 5), 256, GEMM_SMEM>>>(p_apack, p_bt, p_bv, p_acts);
    k_trans<<<dim3(HH/32, Dd/32), 256>>>(dec_v_w, p_wvT);
    k_topk<<<NROW, 256, 65536>>>(p_acts, out);
    k_recon<<<NROW, 256>>>(dec_t_w, dec_t_b, dec_v_b, p_wvT, out);
}

// round 15
// speedup vs baseline: 1.2023x; 1.2023x over previous
#include <cuda_runtime.h>
#include <cuda_bf16.h>
#include <cstdint>

// ---------------- problem constants ----------------
constexpr int   Bb   = 64;
constexpr int   Dd   = 1024;
constexpr int   Tt   = 512;
constexpr int   KC   = 8;
constexpr int   HH   = 16384;
constexpr int   LMAX = 1024;
constexpr int   NROW = Bb + Bb*KC;   // 576
constexpr float GAMMA_C   = 10.0f;
constexpr float EPS_POOL  = 1e-6f;
constexpr float EPS_NORM  = 1e-12f;

// output layout (floats)
constexpr size_t OFF_RECON_V = 0;
constexpr size_t OFF_VIEWS   = OFF_RECON_V + (size_t)Bb*KC*Dd;
constexpr size_t OFF_RECON_T = OFF_VIEWS   + (size_t)Bb*KC*Dd;
constexpr size_t OFF_TGLOBAL = OFF_RECON_T + (size_t)Bb*Dd;
constexpr size_t OFF_LAT_V   = OFF_TGLOBAL + (size_t)Bb*Dd;
constexpr size_t OFF_LAT_T   = OFF_LAT_V   + (size_t)Bb*KC*HH;
constexpr size_t OUT_TOTAL   = OFF_LAT_T   + (size_t)Bb*HH;

// ---------------- scratch ----------------
__device__ float g_acts[(size_t)NROW*HH];               // 36 MB
__device__ float g_m[(size_t)Bb*KC*LMAX];
__device__ float g_den[Bb*KC];
__device__ float g_tkv[NROW*32];
__device__ int   g_tki[NROW*32];
__device__ float g_wvT[(size_t)HH*Dd];                  // 64 MB transposed dec_v_w
__device__ __nv_bfloat16 g_apack[(size_t)640*3072];     // [hiX, loX, hiX] (xinv folded)
__device__ __nv_bfloat16 g_bt[(size_t)HH*2048];         // [hiW, loW] text (winv folded)
__device__ __nv_bfloat16 g_bv[(size_t)HH*2048];         // [hiW, loW] views (winv folded)

// ---------------- PTX helpers ----------------
__device__ __forceinline__ uint32_t smem_u32(const void* p){
    uint32_t a; asm("{ .reg .u64 t; cvta.to.shared.u64 t, %1; cvt.u32.u64 %0, t; }" : "=r"(a) : "l"(p));
    return a;
}
__device__ __forceinline__ void fma2(unsigned long long &c, unsigned long long a, unsigned long long b){
    asm("fma.rn.f32x2 %0, %1, %2, %0;" : "+l"(c) : "l"(a), "l"(b));
}
__device__ __forceinline__ unsigned long long dup2(float x){
    unsigned long long r; asm("mov.b64 %0, {%1, %1};" : "=l"(r) : "f"(x)); return r;
}
__device__ __forceinline__ float2 unpk(unsigned long long v){
    float2 r; asm("mov.b64 {%0, %1}, %2;" : "=f"(r.x), "=f"(r.y) : "l"(v)); return r;
}
__device__ __forceinline__ void cp_async16(uint32_t s, const void* g){
    asm volatile("cp.async.cg.shared.global [%0], [%1], 16;" :: "r"(s), "l"(g));
}
#define CP_COMMIT() asm volatile("cp.async.commit_group;" ::: "memory")
#define CP_WAIT2()  asm volatile("cp.async.wait_group 2;" ::: "memory")

__device__ __forceinline__ void ldm_x4(uint32_t* r, uint32_t addr){
    asm volatile("ldmatrix.sync.aligned.m8n8.x4.shared.b16 {%0,%1,%2,%3}, [%4];"
        : "=r"(r[0]), "=r"(r[1]), "=r"(r[2]), "=r"(r[3]) : "r"(addr));
}
__device__ __forceinline__ void mma16816(float* c, const uint32_t* a, const uint32_t* b){
    asm volatile("mma.sync.aligned.m16n8k16.row.col.f32.bf16.bf16.f32 "
        "{%0,%1,%2,%3}, {%4,%5,%6,%7}, {%8,%9}, {%0,%1,%2,%3};"
        : "+f"(c[0]), "+f"(c[1]), "+f"(c[2]), "+f"(c[3])
        : "r"(a[0]), "r"(a[1]), "r"(a[2]), "r"(a[3]), "r"(b[0]), "r"(b[1]));
}

// ---------------- 1. text global pooling ----------------
__global__ void k_tglobal(const float* __restrict__ t_pad, const float* __restrict__ t_mask,
                          float* __restrict__ out)
{
    int blk = blockIdx.x;               // 256 blocks = 64 b x 4 chunks
    int b = blk >> 2, ch = blk & 3;
    int tid = threadIdx.x;              // 256
    __shared__ float sm[Tt];
    __shared__ float s_inv;
    for (int t = tid; t < Tt; t += 256) sm[t] = t_mask[b*Tt + t];
    __syncthreads();
    if (tid == 0){
        float s = 0.f;
        for (int t = 0; t < Tt; t++) s += sm[t];
        s_inv = 1.f / (s + EPS_POOL);
    }
    __syncthreads();
    int d0 = ch*256 + tid;
    const float* tp = t_pad + (size_t)b*Tt*Dd + d0;
    float acc = 0.f;
    #pragma unroll 4
    for (int t = 0; t < Tt; t++) acc += tp[(size_t)t*Dd] * sm[t];
    out[OFF_TGLOBAL + (size_t)b*Dd + d0] = acc * s_inv;
}

// ---------------- 2. gaussian weights ----------------
__global__ void k_mden(const float* __restrict__ centers, const int* __restrict__ grid_thws)
{
    int b = blockIdx.x, tid = threadIdx.x;
    int Hg = grid_thws[1], Wg = grid_thws[2];
    int L  = Hg * Wg;
    __shared__ float partial[KC][8];
    int lane = tid & 31, warp = tid >> 5;
    for (int k = 0; k < KC; k++){
        float cx = centers[(b*KC+k)*2 + 0];
        float cy = centers[(b*KC+k)*2 + 1];
        float local = 0.f;
        for (int l = tid; l < L; l += 256){
            int iy = l / Wg, ix = l % Wg;
            float px = (ix + 0.5f) / (float)Wg;
            float py = (iy + 0.5f) / (float)Hg;
            float dx = cx - px, dy = cy - py;
            float m = expf(-GAMMA_C * (dx*dx + dy*dy));
            g_m[((size_t)b*KC + k)*LMAX + l] = m;
            local += m;
        }
        #pragma unroll
        for (int off = 16; off; off >>= 1) local += __shfl_down_sync(0xffffffffu, local, off);
        if (lane == 0) partial[k][warp] = local;
    }
    __syncthreads();
    if (tid < KC){
        float s = 0.f;
        #pragma unroll
        for (int w = 0; w < 8; w++) s += partial[tid][w];
        g_den[b*KC + tid] = s;
    }
}

// ---------------- 3. gaussian view pooling (f32x2) ----------------
__global__ void k_views(const float* __restrict__ v_pad, float* __restrict__ out)
{
    extern __shared__ unsigned long long ms2[];   // 64 KB
    int blk = blockIdx.x;
    int b = blk >> 2, ch = blk & 3;
    int tid = threadIdx.x;               // 128
    for (int i = tid; i < KC*LMAX; i += 128) ms2[i] = dup2(g_m[(size_t)b*KC*LMAX + i]);
    __syncthreads();

    int d0 = ch*256 + tid*2;
    const float* vp = v_pad + (size_t)b*LMAX*Dd + d0;
    unsigned long long acc[KC];
    #pragma unroll
    for (int k = 0; k < KC; k++) acc[k] = 0ull;

    for (int l = 0; l < LMAX; l++){
        unsigned long long v = *(const unsigned long long*)(vp + (size_t)l*Dd);
        #pragma unroll
        for (int k = 0; k < KC; k++) fma2(acc[k], ms2[k*LMAX + l], v);
    }
    #pragma unroll
    for (int k = 0; k < KC; k++){
        float inv = 1.f / (g_den[b*KC + k] + EPS_POOL);
        float2 a = unpk(acc[k]);
        float2 o = make_float2(a.x*inv, a.y*inv);
        *(float2*)(out + OFF_VIEWS + ((size_t)(b*KC + k))*Dd + d0) = o;
    }
}

// ---------------- 4. pack B (both enc matrices): warp-per-row, winv folded ----------------
__global__ void k_packb(const float* __restrict__ enc_t, const float* __restrict__ enc_v,
                        __nv_bfloat16* __restrict__ bt, __nv_bfloat16* __restrict__ bv)
{
    const float* enc = blockIdx.y ? enc_v : enc_t;
    __nv_bfloat16* Bp = blockIdx.y ? bv : bt;
    int warp = threadIdx.x >> 5, lane = threadIdx.x & 31;
    int n = blockIdx.x*8 + warp;

    const float4* src = (const float4*)(enc + (size_t)n*Dd);
    float4 v[8];
    float s = 0.f;
    #pragma unroll
    for (int i = 0; i < 8; i++){
        v[i] = src[i*32 + lane];
        s += v[i].x*v[i].x + v[i].y*v[i].y + v[i].z*v[i].z + v[i].w*v[i].w;
    }
    #pragma unroll
    for (int off = 16; off; off >>= 1) s += __shfl_xor_sync(0xffffffffu, s, off);
    float sc = 1.f / fmaxf(sqrtf(s), EPS_NORM);

    __nv_bfloat16* row = Bp + (size_t)n*2048;
    #pragma unroll
    for (int i = 0; i < 8; i++){
        float xs[4] = {v[i].x*sc, v[i].y*sc, v[i].z*sc, v[i].w*sc};
        union { __nv_bfloat16 b[4]; unsigned long long u; } uh, ul;
        #pragma unroll
        for (int j = 0; j < 4; j++){
            __nv_bfloat16 h = __float2bfloat16(xs[j]);
            uh.b[j] = h;
            ul.b[j] = __float2bfloat16(xs[j] - __bfloat162float(h));
        }
        int e = (i*32 + lane)*4;
        *(unsigned long long*)(row + e)        = uh.u;
        *(unsigned long long*)(row + 1024 + e) = ul.u;
    }
}

// ---------------- 5. pack A with fused row norm (rows 64..127 pad zeros) ----------------
__global__ void k_packa(const float* __restrict__ out, __nv_bfloat16* __restrict__ Ap)
{
    int r = blockIdx.x, tid = threadIdx.x;     // 640 blocks, 256 threads
    float4 v = make_float4(0.f, 0.f, 0.f, 0.f);
    if (r < 64)        v = ((const float4*)(out + OFF_TGLOBAL + (size_t)r*Dd))[tid];
    else if (r >= 128) v = ((const float4*)(out + OFF_VIEWS + (size_t)(r-128)*Dd))[tid];

    float s = v.x*v.x + v.y*v.y + v.z*v.z + v.w*v.w;
    __shared__ float ws[8];
    __shared__ float s_scale;
    int lane = tid & 31, warp = tid >> 5;
    #pragma unroll
    for (int off = 16; off; off >>= 1) s += __shfl_down_sync(0xffffffffu, s, off);
    if (lane == 0) ws[warp] = s;
    __syncthreads();
    if (tid == 0){
        float t = 0.f;
        #pragma unroll
        for (int w = 0; w < 8; w++) t += ws[w];
        s_scale = 1.f / fmaxf(sqrtf(t), EPS_NORM);
    }
    __syncthreads();
    float sc = s_scale;

    float xs[4] = {v.x*sc, v.y*sc, v.z*sc, v.w*sc};
    union { __nv_bfloat16 b[4]; unsigned long long u; } uh, ul;
    #pragma unroll
    for (int i = 0; i < 4; i++){
        __nv_bfloat16 h = __float2bfloat16(xs[i]);
        uh.b[i] = h;
        ul.b[i] = __float2bfloat16(xs[i] - __bfloat162float(h));
    }
    __nv_bfloat16* row = Ap + (size_t)r*3072;
    *(unsigned long long*)(row + tid*4)        = uh.u;
    *(unsigned long long*)(row + 1024 + tid*4) = ul.u;
    *(unsigned long long*)(row + 2048 + tid*4) = uh.u;
}

// ---------------- 6. merged bf16-split GEMM, software-pipelined fragments ----------------
// grid (HH/128, 5): by=0 text (Mvalid=64), by=1..4 views (Mvalid=128).
// CTA tile 128x128, K=3072 in 48 chunks of 64; 4-stage cp.async, 1 CTA/SM
// (255-reg budget -> double-buffered ldmatrix fragments hide LDSM latency).
constexpr int STAGE_BYTES = 32768;                 // A 16KB + B 16KB
constexpr int GEMM_SMEM   = 1024 + 4*STAGE_BYTES;  // 132 KB

__device__ __forceinline__ int b_off(int c){
    return (c < 32) ? ((c & 15) * 128) : (2048 + (c - 32) * 128);
}

__device__ __forceinline__ void load_chunk(const char* Ab, const char* Bbp,
                                           int aOff, int bOff,
                                           uint32_t smA, uint32_t smB, int tid)
{
    #pragma unroll
    for (int i = 0; i < 4; i++){            // A: 128 rows x 8 segs
        int idx = i*256 + tid;
        int row = idx >> 3, seg = idx & 7;
        uint32_t col = (uint32_t)(seg*16) ^ (uint32_t)((row & 7) << 4);
        cp_async16(smA + row*128 + col, Ab + (size_t)row*6144 + aOff + seg*16);
    }
    #pragma unroll
    for (int i = 0; i < 4; i++){            // B: 128 rows x 8 segs
        int idx = i*256 + tid;
        int row = idx >> 3, seg = idx & 7;
        uint32_t col = (uint32_t)(seg*16) ^ (uint32_t)((row & 7) << 4);
        cp_async16(smB + row*128 + col, Bbp + (size_t)row*4096 + bOff + seg*16);
    }
}

__global__ void __launch_bounds__(256, 1)
k_gemm_mma(const __nv_bfloat16* __restrict__ Apack,
           const __nv_bfloat16* __restrict__ Bt, const __nv_bfloat16* __restrict__ Bv,
           float* __restrict__ acts)
{
    extern __shared__ char dsm[];
    const int tid = threadIdx.x;
    const int by  = blockIdx.y;
    const int bn0 = blockIdx.x * 128;
    const int Mvalid = by ? 128 : 64;
    const __nv_bfloat16* Bpack = by ? Bv : Bt;
    float* actsBase = acts + (by ? (size_t)(64 + (by-1)*128)*HH : 0);

    uint32_t sb = (smem_u32(dsm) + 1023u) & ~1023u;
    const char* Ab  = (const char*)(Apack + (size_t)by*128*3072);
    const char* Bbp = (const char*)(Bpack + (size_t)bn0*2048);

    // prologue: chunks 0..2 into stages 0..2
    #pragma unroll
    for (int c = 0; c < 3; c++){
        uint32_t st = sb + c*STAGE_BYTES;
        load_chunk(Ab, Bbp, c*128, b_off(c), st, st + 16384, tid);
        CP_COMMIT();
    }

    const int w = tid >> 5, lane = tid & 31;
    const int wm = w & 3, wn = w >> 2;        // 4 x 2 warp grid; warp tile 32(M) x 64(N)

    float acc[2][8][4];
    #pragma unroll
    for (int mt = 0; mt < 2; mt++)
        #pragma unroll
        for (int nt = 0; nt < 8; nt++)
            #pragma unroll
            for (int j = 0; j < 4; j++) acc[mt][nt][j] = 0.f;

    const int arow  = wm*32 + (lane & 15);
    const int acolh = (lane >> 4) * 16;
    const int brow  = wn*64 + (lane & 7) + ((lane >> 4) << 3);
    const int bcolh = ((lane >> 3) & 1) * 16;

    uint32_t af[2][2][4], bf[2][4][4];   // double-buffered fragments

    for (int c = 0; c < 48; c++){
        CP_WAIT2();
        __syncthreads();
        // issue gmem loads for chunk c+3 (stage (c+3)&3; its previous content
        // was consumed in iteration c-1 and is fenced by the syncthreads above)
        int nc = c + 3;
        if (nc < 48){
            uint32_t st = sb + (nc & 3)*STAGE_BYTES;
            load_chunk(Ab, Bbp, nc*128, b_off(nc), st, st + 16384, tid);
            CP_COMMIT();
        }
        uint32_t stA = sb + (c & 3)*STAGE_BYTES;
        uint32_t stB = stA + 16384;

        // preload fragments for ks=0
        #pragma unroll
        for (int mt = 0; mt < 2; mt++){
            int r = arow + mt*16;
            uint32_t col = (uint32_t)(acolh) ^ (uint32_t)((r & 7) << 4);
            ldm_x4(af[0][mt], stA + r*128 + col);
        }
        #pragma unroll
        for (int nt = 0; nt < 4; nt++){
            int r = brow + nt*16;
            uint32_t col = (uint32_t)(bcolh) ^ (uint32_t)((r & 7) << 4);
            ldm_x4(bf[0][nt], stB + r*128 + col);
        }

        #pragma unroll
        for (int ks = 0; ks < 4; ks++){
            const int cur = ks & 1, nxt = cur ^ 1;
            // prefetch ks+1 fragments BEFORE issuing this step's mma batch
            if (ks < 3){
                int kb = (ks+1)*32;
                #pragma unroll
                for (int mt = 0; mt < 2; mt++){
                    int r = arow + mt*16;
                    uint32_t col = (uint32_t)(kb + acolh) ^ (uint32_t)((r & 7) << 4);
                    ldm_x4(af[nxt][mt], stA + r*128 + col);
                }
                #pragma unroll
                for (int nt = 0; nt < 4; nt++){
                    int r = brow + nt*16;
                    uint32_t col = (uint32_t)(kb + bcolh) ^ (uint32_t)((r & 7) << 4);
                    ldm_x4(bf[nxt][nt], stB + r*128 + col);
                }
            }
            #pragma unroll
            for (int mt = 0; mt < 2; mt++)
                #pragma unroll
                for (int nt = 0; nt < 4; nt++){
                    mma16816(acc[mt][nt*2],   af[cur][mt], bf[cur][nt]);
                    mma16816(acc[mt][nt*2+1], af[cur][mt], bf[cur][nt] + 2);
                }
        }
    }

    // epilogue: cos -> acts transform, direct global stores
    const int r0 = lane >> 2;
    const int cb = (lane & 3) * 2;
    #pragma unroll
    for (int mt = 0; mt < 2; mt++){
        #pragma unroll
        for (int half = 0; half < 2; half++){
            int ml = wm*32 + mt*16 + half*8 + r0;
            if (ml < Mvalid){
                float* dst = actsBase + (size_t)ml*HH + bn0 + wn*64 + cb;
                #pragma unroll
                for (int nt = 0; nt < 8; nt++){
                    float v0 = acc[mt][nt][half*2 + 0];
                    float v1 = acc[mt][nt][half*2 + 1];
                    float c0 = fminf(1.f, fmaxf(-1.f, v0));
                    float c1 = fminf(1.f, fmaxf(-1.f, v1));
                    float2 o;
                    o.x = 2.f - sqrtf(fmaxf(0.f, 2.f - 2.f*c0));
                    o.y = 2.f - sqrtf(fmaxf(0.f, 2.f - 2.f*c1));
                    *(float2*)(dst + nt*8) = o;
                }
            }
        }
    }
}

// ---------------- 7. transpose dec_v_w [D,H] -> g_wvT [H,D] ----------------
__global__ void k_trans(const float* __restrict__ W, float* __restrict__ WT)
{
    __shared__ float t[32][33];
    int tx = threadIdx.x & 31, ty = threadIdx.x >> 5;   // 32 x 8
    int h0 = blockIdx.x * 32, d0 = blockIdx.y * 32;
    #pragma unroll
    for (int j = 0; j < 32; j += 8)
        t[ty+j][tx] = W[(size_t)(d0+ty+j)*HH + h0 + tx];
    __syncthreads();
    #pragma unroll
    for (int j = 0; j < 32; j += 8)
        WT[(size_t)(h0+ty+j)*Dd + d0 + tx] = t[tx][ty+j];
}

// ---------------- 8. top-32 per row: local top-6 + candidate select ----------------
__global__ void k_topk(const float* __restrict__ acts, float* __restrict__ out)
{
    extern __shared__ float sv[];   // 64 KB (fallback only)
    __shared__ unsigned long long red[8];
    __shared__ unsigned long long s_win;
    __shared__ float selv[32];
    __shared__ int   seli[32];

    int n = blockIdx.x, tid = threadIdx.x;    // 256 threads
    int lane = tid & 31, warp = tid >> 5;
    const float* row = acts + (size_t)n*HH;
    float* latrow = (n < Bb) ? out + OFF_LAT_T + (size_t)n*HH
                             : out + OFF_LAT_V + (size_t)(n-Bb)*HH;

    float4 z = make_float4(0.f, 0.f, 0.f, 0.f);
    for (int i = tid; i < HH/4; i += 256) ((float4*)latrow)[i] = z;

    unsigned long long loc[6] = {0ull,0ull,0ull,0ull,0ull,0ull};
    for (int i = tid; i < HH; i += 256){
        unsigned int bits = __float_as_uint(row[i]);
        unsigned long long pk = ((unsigned long long)bits << 32) | (unsigned int)(HH-1-i);
        if (pk > loc[5]){
            loc[5] = pk;
            #pragma unroll
            for (int j = 5; j > 0; j--){
                if (loc[j] > loc[j-1]){ unsigned long long t = loc[j]; loc[j] = loc[j-1]; loc[j-1] = t; }
            }
        }
    }
    const unsigned long long orig5 = loc[5];

    for (int p = 0; p < 32; p++){
        unsigned long long best = loc[0];
        #pragma unroll
        for (int j = 1; j < 6; j++) best = (loc[j] > best) ? loc[j] : best;
        #pragma unroll
        for (int off = 16; off; off >>= 1){
            unsigned long long o = __shfl_down_sync(0xffffffffu, best, off);
            best = (o > best) ? o : best;
        }
        if (lane == 0) red[warp] = best;
        __syncthreads();
        if (tid < 32){
            unsigned long long b2 = (tid < 8) ? red[tid] : 0ull;
            #pragma unroll
            for (int off = 4; off; off >>= 1){
                unsigned long long o = __shfl_down_sync(0xffffffffu, b2, off);
                b2 = (o > b2) ? o : b2;
            }
            if (tid == 0){
                s_win = b2;
                selv[p] = __uint_as_float((unsigned int)(b2 >> 32));
                seli[p] = HH - 1 - (int)(unsigned int)(b2 & 0xffffffffull);
            }
        }
        __syncthreads();
        unsigned long long wk = s_win;
        #pragma unroll
        for (int j = 0; j < 6; j++) if (loc[j] == wk) loc[j] = 0ull;
    }

    unsigned long long kth = s_win;
    int bad = (orig5 > kth) ? 1 : 0;
    if (__syncthreads_or(bad)){
        for (int i = tid; i < HH; i += 256) sv[i] = row[i];
        __syncthreads();
        for (int p = 0; p < 32; p++){
            unsigned long long best = 0ull;
            for (int i = tid; i < HH; i += 256){
                unsigned int bits = __float_as_uint(sv[i]);
                unsigned long long pk = ((unsigned long long)bits << 32) | (unsigned int)(HH-1-i);
                best = (pk > best) ? pk : best;
            }
            #pragma unroll
            for (int off = 16; off; off >>= 1){
                unsigned long long o = __shfl_down_sync(0xffffffffu, best, off);
                best = (o > best) ? o : best;
            }
            if (lane == 0) red[warp] = best;
            __syncthreads();
            if (tid < 32){
                unsigned long long b2 = (tid < 8) ? red[tid] : 0ull;
                #pragma unroll
                for (int off = 4; off; off >>= 1){
                    unsigned long long o = __shfl_down_sync(0xffffffffu, b2, off);
                    b2 = (o > b2) ? o : b2;
                }
                if (tid == 0){
                    int idx = HH - 1 - (int)(unsigned int)(b2 & 0xffffffffull);
                    selv[p] = __uint_as_float((unsigned int)(b2 >> 32));
                    seli[p] = idx;
                    sv[idx] = 0.0f;
                }
            }
            __syncthreads();
        }
    }

    if (tid < 32){
        float v = selv[tid]; int h = seli[tid];
        latrow[h] = v;
        g_tkv[n*32 + tid] = v;
        g_tki[n*32 + tid] = h;
    }
}

// ---------------- 9. sparse reconstruction ----------------
__global__ void k_recon(const float* __restrict__ dec_t_w, const float* __restrict__ dec_t_b,
                        const float* __restrict__ dec_v_b, const float* __restrict__ wvT,
                        float* __restrict__ out)
{
    int n = blockIdx.x, tid = threadIdx.x;
    __shared__ float vk[32];
    __shared__ int   hk[32];
    if (tid < 32){ vk[tid] = g_tkv[n*32+tid]; hk[tid] = g_tki[n*32+tid]; }
    __syncthreads();

    if (n < Bb){
        float* dst = out + OFF_RECON_T + (size_t)n*Dd;
        for (int d = tid; d < Dd; d += 256){
            float acc = dec_t_b[d];
            const float* wr = dec_t_w + (size_t)d*HH;
            #pragma unroll
            for (int k = 0; k < 32; k++) acc += vk[k] * wr[hk[k]];
            dst[d] = acc;
        }
    } else {
        float* dst = out + OFF_RECON_V + (size_t)(n-Bb)*Dd;
        float4 acc = ((const float4*)dec_v_b)[tid];
        #pragma unroll
        for (int k = 0; k < 32; k++){
            float4 wv = ((const float4*)(wvT + (size_t)hk[k]*Dd))[tid];
            float v = vk[k];
            acc.x += v*wv.x; acc.y += v*wv.y; acc.z += v*wv.z; acc.w += v*wv.w;
        }
        ((float4*)dst)[tid] = acc;
    }
}

// ---------------- launch ----------------
extern "C" void kernel_launch(void* const* d_in, const int* in_sizes, int n_in,
                              void* d_out, int out_size)
{
    const float* v_pad    = (const float*)d_in[0];
    const int*   grid_thws= (const int*)  d_in[2];
    const float* t_pad    = (const float*)d_in[3];
    const float* t_mask   = (const float*)d_in[4];
    const float* centers  = (const float*)d_in[5];
    const float* enc_v    = (const float*)d_in[6];
    const float* dec_v_w  = (const float*)d_in[7];
    const float* dec_v_b  = (const float*)d_in[8];
    const float* enc_t    = (const float*)d_in[9];
    const float* dec_t_w  = (const float*)d_in[10];
    const float* dec_t_b  = (const float*)d_in[11];
    float* out = (float*)d_out;

    float *p_acts, *p_wvT;
    __nv_bfloat16 *p_apack, *p_bt, *p_bv;
    cudaGetSymbolAddress((void**)&p_acts,  g_acts);
    cudaGetSymbolAddress((void**)&p_wvT,   g_wvT);
    cudaGetSymbolAddress((void**)&p_apack, g_apack);
    cudaGetSymbolAddress((void**)&p_bt,    g_bt);
    cudaGetSymbolAddress((void**)&p_bv,    g_bv);

    cudaFuncSetAttribute(k_views,    cudaFuncAttributeMaxDynamicSharedMemorySize, 65536);
    cudaFuncSetAttribute(k_gemm_mma, cudaFuncAttributeMaxDynamicSharedMemorySize, GEMM_SMEM);
    cudaFuncSetAttribute(k_topk,     cudaFuncAttributeMaxDynamicSharedMemorySize, 65536);

    k_tglobal<<<Bb*4, 256>>>(t_pad, t_mask, out);
    k_mden<<<Bb, 256>>>(centers, grid_thws);
    k_views<<<Bb*4, 128, 65536>>>(v_pad, out);
    k_packb<<<dim3(HH/8, 2), 256>>>(enc_t, enc_v, p_bt, p_bv);
    k_packa<<<640, 256>>>(out, p_apack);
    k_gemm_mma<<<dim3(HH/128, 5), 256, GEMM_SMEM>>>(p_apack, p_bt, p_bv, p_acts);
    k_trans<<<dim3(HH/32, Dd/32), 256>>>(dec_v_w, p_wvT);
    k_topk<<<NROW, 256, 65536>>>(p_acts, out);
    k_recon<<<NROW, 256>>>(dec_t_w, dec_t_b, dec_v_b, p_wvT, out);
}

// round 16
// speedup vs baseline: 1.3538x; 1.1260x over previous
#include <cuda_runtime.h>
#include <cuda_bf16.h>
#include <cstdint>

// ---------------- problem constants ----------------
constexpr int   Bb   = 64;
constexpr int   Dd   = 1024;
constexpr int   Tt   = 512;
constexpr int   KC   = 8;
constexpr int   HH   = 16384;
constexpr int   LMAX = 1024;
constexpr int   NROW = Bb + Bb*KC;   // 576
constexpr float GAMMA_C   = 10.0f;
constexpr float EPS_POOL  = 1e-6f;
constexpr float EPS_NORM  = 1e-12f;
constexpr float THR_2DELTA = 0.008f;   // 2 * worst-case |true_cos - hi·hi| (<= 0.004)

// output layout (floats)
constexpr size_t OFF_RECON_V = 0;
constexpr size_t OFF_VIEWS   = OFF_RECON_V + (size_t)Bb*KC*Dd;
constexpr size_t OFF_RECON_T = OFF_VIEWS   + (size_t)Bb*KC*Dd;
constexpr size_t OFF_TGLOBAL = OFF_RECON_T + (size_t)Bb*Dd;
constexpr size_t OFF_LAT_V   = OFF_TGLOBAL + (size_t)Bb*Dd;
constexpr size_t OFF_LAT_T   = OFF_LAT_V   + (size_t)Bb*KC*HH;
constexpr size_t OUT_TOTAL   = OFF_LAT_T   + (size_t)Bb*HH;

// ---------------- scratch ----------------
__device__ float g_acts[(size_t)NROW*HH];               // approx cos, 36 MB
__device__ float g_m[(size_t)Bb*KC*LMAX];
__device__ float g_den[Bb*KC];
__device__ float g_tkv[NROW*32];
__device__ int   g_tki[NROW*32];
__device__ float g_wvT[(size_t)HH*Dd];                  // 64 MB transposed dec_v_w
__device__ __nv_bfloat16 g_apack[(size_t)640*2048];     // [hiX, loX] (xinv folded)
__device__ __nv_bfloat16 g_bt[(size_t)HH*2048];         // [hiW, loW] text (winv folded)
__device__ __nv_bfloat16 g_bv[(size_t)HH*2048];         // [hiW, loW] views (winv folded)

// ---------------- PTX helpers ----------------
__device__ __forceinline__ uint32_t smem_u32(const void* p){
    uint32_t a; asm("{ .reg .u64 t; cvta.to.shared.u64 t, %1; cvt.u32.u64 %0, t; }" : "=r"(a) : "l"(p));
    return a;
}
__device__ __forceinline__ void fma2(unsigned long long &c, unsigned long long a, unsigned long long b){
    asm("fma.rn.f32x2 %0, %1, %2, %0;" : "+l"(c) : "l"(a), "l"(b));
}
__device__ __forceinline__ unsigned long long dup2(float x){
    unsigned long long r; asm("mov.b64 %0, {%1, %1};" : "=l"(r) : "f"(x)); return r;
}
__device__ __forceinline__ float2 unpk(unsigned long long v){
    float2 r; asm("mov.b64 {%0, %1}, %2;" : "=f"(r.x), "=f"(r.y) : "l"(v)); return r;
}
__device__ __forceinline__ void cp_async16(uint32_t s, const void* g){
    asm volatile("cp.async.cg.shared.global [%0], [%1], 16;" :: "r"(s), "l"(g));
}
#define CP_COMMIT() asm volatile("cp.async.commit_group;" ::: "memory")
#define CP_WAIT1()  asm volatile("cp.async.wait_group 1;" ::: "memory")

__device__ __forceinline__ void ldm_x4(uint32_t* r, uint32_t addr){
    asm volatile("ldmatrix.sync.aligned.m8n8.x4.shared.b16 {%0,%1,%2,%3}, [%4];"
        : "=r"(r[0]), "=r"(r[1]), "=r"(r[2]), "=r"(r[3]) : "r"(addr));
}
__device__ __forceinline__ void mma16816(float* c, const uint32_t* a, const uint32_t* b){
    asm volatile("mma.sync.aligned.m16n8k16.row.col.f32.bf16.bf16.f32 "
        "{%0,%1,%2,%3}, {%4,%5,%6,%7}, {%8,%9}, {%0,%1,%2,%3};"
        : "+f"(c[0]), "+f"(c[1]), "+f"(c[2]), "+f"(c[3])
        : "r"(a[0]), "r"(a[1]), "r"(a[2]), "r"(a[3]), "r"(b[0]), "r"(b[1]));
}
// order-preserving map for float bits (handles negatives)
__device__ __forceinline__ unsigned int fmap(float f){
    unsigned int b = __float_as_uint(f);
    return b ^ (((int)b >> 31) | 0x80000000u);
}
__device__ __forceinline__ float funmap(unsigned int m){
    unsigned int rb = (m & 0x80000000u) ? (m ^ 0x80000000u) : ~m;
    return __uint_as_float(rb);
}
__device__ __forceinline__ float acts_of_cos(float c){
    float cc = fminf(1.f, fmaxf(-1.f, c));
    return 2.f - sqrtf(fmaxf(0.f, 2.f - 2.f*cc));
}

// ---------------- 1. text global pooling ----------------
__global__ void k_tglobal(const float* __restrict__ t_pad, const float* __restrict__ t_mask,
                          float* __restrict__ out)
{
    int blk = blockIdx.x;
    int b = blk >> 2, ch = blk & 3;
    int tid = threadIdx.x;
    __shared__ float sm[Tt];
    __shared__ float s_inv;
    for (int t = tid; t < Tt; t += 256) sm[t] = t_mask[b*Tt + t];
    __syncthreads();
    if (tid == 0){
        float s = 0.f;
        for (int t = 0; t < Tt; t++) s += sm[t];
        s_inv = 1.f / (s + EPS_POOL);
    }
    __syncthreads();
    int d0 = ch*256 + tid;
    const float* tp = t_pad + (size_t)b*Tt*Dd + d0;
    float acc = 0.f;
    #pragma unroll 4
    for (int t = 0; t < Tt; t++) acc += tp[(size_t)t*Dd] * sm[t];
    out[OFF_TGLOBAL + (size_t)b*Dd + d0] = acc * s_inv;
}

// ---------------- 2. gaussian weights ----------------
__global__ void k_mden(const float* __restrict__ centers, const int* __restrict__ grid_thws)
{
    int b = blockIdx.x, tid = threadIdx.x;
    int Hg = grid_thws[1], Wg = grid_thws[2];
    int L  = Hg * Wg;
    __shared__ float partial[KC][8];
    int lane = tid & 31, warp = tid >> 5;
    for (int k = 0; k < KC; k++){
        float cx = centers[(b*KC+k)*2 + 0];
        float cy = centers[(b*KC+k)*2 + 1];
        float local = 0.f;
        for (int l = tid; l < L; l += 256){
            int iy = l / Wg, ix = l % Wg;
            float px = (ix + 0.5f) / (float)Wg;
            float py = (iy + 0.5f) / (float)Hg;
            float dx = cx - px, dy = cy - py;
            float m = expf(-GAMMA_C * (dx*dx + dy*dy));
            g_m[((size_t)b*KC + k)*LMAX + l] = m;
            local += m;
        }
        #pragma unroll
        for (int off = 16; off; off >>= 1) local += __shfl_down_sync(0xffffffffu, local, off);
        if (lane == 0) partial[k][warp] = local;
    }
    __syncthreads();
    if (tid < KC){
        float s = 0.f;
        #pragma unroll
        for (int w = 0; w < 8; w++) s += partial[tid][w];
        g_den[b*KC + tid] = s;
    }
}

// ---------------- 3. gaussian view pooling (f32x2) ----------------
__global__ void k_views(const float* __restrict__ v_pad, float* __restrict__ out)
{
    extern __shared__ unsigned long long ms2[];
    int blk = blockIdx.x;
    int b = blk >> 2, ch = blk & 3;
    int tid = threadIdx.x;               // 128
    for (int i = tid; i < KC*LMAX; i += 128) ms2[i] = dup2(g_m[(size_t)b*KC*LMAX + i]);
    __syncthreads();

    int d0 = ch*256 + tid*2;
    const float* vp = v_pad + (size_t)b*LMAX*Dd + d0;
    unsigned long long acc[KC];
    #pragma unroll
    for (int k = 0; k < KC; k++) acc[k] = 0ull;

    for (int l = 0; l < LMAX; l++){
        unsigned long long v = *(const unsigned long long*)(vp + (size_t)l*Dd);
        #pragma unroll
        for (int k = 0; k < KC; k++) fma2(acc[k], ms2[k*LMAX + l], v);
    }
    #pragma unroll
    for (int k = 0; k < KC; k++){
        float inv = 1.f / (g_den[b*KC + k] + EPS_POOL);
        float2 a = unpk(acc[k]);
        float2 o = make_float2(a.x*inv, a.y*inv);
        *(float2*)(out + OFF_VIEWS + ((size_t)(b*KC + k))*Dd + d0) = o;
    }
}

// ---------------- 4. pack B (both enc matrices): warp-per-row, winv folded ----------------
__global__ void k_packb(const float* __restrict__ enc_t, const float* __restrict__ enc_v,
                        __nv_bfloat16* __restrict__ bt, __nv_bfloat16* __restrict__ bv)
{
    const float* enc = blockIdx.y ? enc_v : enc_t;
    __nv_bfloat16* Bp = blockIdx.y ? bv : bt;
    int warp = threadIdx.x >> 5, lane = threadIdx.x & 31;
    int n = blockIdx.x*8 + warp;

    const float4* src = (const float4*)(enc + (size_t)n*Dd);
    float4 v[8];
    float s = 0.f;
    #pragma unroll
    for (int i = 0; i < 8; i++){
        v[i] = src[i*32 + lane];
        s += v[i].x*v[i].x + v[i].y*v[i].y + v[i].z*v[i].z + v[i].w*v[i].w;
    }
    #pragma unroll
    for (int off = 16; off; off >>= 1) s += __shfl_xor_sync(0xffffffffu, s, off);
    float sc = 1.f / fmaxf(sqrtf(s), EPS_NORM);

    __nv_bfloat16* row = Bp + (size_t)n*2048;
    #pragma unroll
    for (int i = 0; i < 8; i++){
        float xs[4] = {v[i].x*sc, v[i].y*sc, v[i].z*sc, v[i].w*sc};
        union { __nv_bfloat16 b[4]; unsigned long long u; } uh, ul;
        #pragma unroll
        for (int j = 0; j < 4; j++){
            __nv_bfloat16 h = __float2bfloat16(xs[j]);
            uh.b[j] = h;
            ul.b[j] = __float2bfloat16(xs[j] - __bfloat162float(h));
        }
        int e = (i*32 + lane)*4;
        *(unsigned long long*)(row + e)        = uh.u;
        *(unsigned long long*)(row + 1024 + e) = ul.u;
    }
}

// ---------------- 5. pack A [hi, lo] with fused row norm (rows 64..127 pad zeros) ----------------
__global__ void k_packa(const float* __restrict__ out, __nv_bfloat16* __restrict__ Ap)
{
    int r = blockIdx.x, tid = threadIdx.x;     // 640 blocks, 256 threads
    float4 v = make_float4(0.f, 0.f, 0.f, 0.f);
    if (r < 64)        v = ((const float4*)(out + OFF_TGLOBAL + (size_t)r*Dd))[tid];
    else if (r >= 128) v = ((const float4*)(out + OFF_VIEWS + (size_t)(r-128)*Dd))[tid];

    float s = v.x*v.x + v.y*v.y + v.z*v.z + v.w*v.w;
    __shared__ float ws[8];
    __shared__ float s_scale;
    int lane = tid & 31, warp = tid >> 5;
    #pragma unroll
    for (int off = 16; off; off >>= 1) s += __shfl_down_sync(0xffffffffu, s, off);
    if (lane == 0) ws[warp] = s;
    __syncthreads();
    if (tid == 0){
        float t = 0.f;
        #pragma unroll
        for (int w = 0; w < 8; w++) t += ws[w];
        s_scale = 1.f / fmaxf(sqrtf(t), EPS_NORM);
    }
    __syncthreads();
    float sc = s_scale;

    float xs[4] = {v.x*sc, v.y*sc, v.z*sc, v.w*sc};
    union { __nv_bfloat16 b[4]; unsigned long long u; } uh, ul;
    #pragma unroll
    for (int i = 0; i < 4; i++){
        __nv_bfloat16 h = __float2bfloat16(xs[i]);
        uh.b[i] = h;
        ul.b[i] = __float2bfloat16(xs[i] - __bfloat162float(h));
    }
    __nv_bfloat16* row = Ap + (size_t)r*2048;
    *(unsigned long long*)(row + tid*4)        = uh.u;
    *(unsigned long long*)(row + 1024 + tid*4) = ul.u;
}

// ---------------- 6. hi-only bf16 GEMM (approx cos), R8 mainloop config ----------------
// grid (HH/128, 5): by=0 text (Mvalid=64), by=1..4 views. K=1024 in 16 chunks.
constexpr int STAGE_BYTES = 32768;                 // A 16KB + B 16KB
constexpr int GEMM_SMEM   = 1024 + 3*STAGE_BYTES;  // ~97 KB

__device__ __forceinline__ void load_chunk(const char* Ab, const char* Bbp, int off,
                                           uint32_t smA, uint32_t smB, int tid)
{
    #pragma unroll
    for (int i = 0; i < 4; i++){            // A: 128 rows x 8 segs (hi region)
        int idx = i*256 + tid;
        int row = idx >> 3, seg = idx & 7;
        uint32_t col = (uint32_t)(seg*16) ^ (uint32_t)((row & 7) << 4);
        cp_async16(smA + row*128 + col, Ab + (size_t)row*4096 + off + seg*16);
    }
    #pragma unroll
    for (int i = 0; i < 4; i++){            // B: 128 rows x 8 segs (hi region)
        int idx = i*256 + tid;
        int row = idx >> 3, seg = idx & 7;
        uint32_t col = (uint32_t)(seg*16) ^ (uint32_t)((row & 7) << 4);
        cp_async16(smB + row*128 + col, Bbp + (size_t)row*4096 + off + seg*16);
    }
}

__global__ void __launch_bounds__(256, 2)
k_gemm_mma(const __nv_bfloat16* __restrict__ Apack,
           const __nv_bfloat16* __restrict__ Bt, const __nv_bfloat16* __restrict__ Bv,
           float* __restrict__ acts)
{
    extern __shared__ char dsm[];
    const int tid = threadIdx.x;
    const int by  = blockIdx.y;
    const int bn0 = blockIdx.x * 128;
    const int Mvalid = by ? 128 : 64;
    const __nv_bfloat16* Bpack = by ? Bv : Bt;
    float* actsBase = acts + (by ? (size_t)(64 + (by-1)*128)*HH : 0);

    uint32_t sb = (smem_u32(dsm) + 1023u) & ~1023u;
    const char* Ab  = (const char*)(Apack + (size_t)by*128*2048);
    const char* Bbp = (const char*)(Bpack + (size_t)bn0*2048);

    #pragma unroll
    for (int c = 0; c < 2; c++){
        uint32_t st = sb + c*STAGE_BYTES;
        load_chunk(Ab, Bbp, c*128, st, st + 16384, tid);
        CP_COMMIT();
    }

    const int w = tid >> 5, lane = tid & 31;
    const int wm = w & 3, wn = w >> 2;

    float acc[2][8][4];
    #pragma unroll
    for (int mt = 0; mt < 2; mt++)
        #pragma unroll
        for (int nt = 0; nt < 8; nt++)
            #pragma unroll
            for (int j = 0; j < 4; j++) acc[mt][nt][j] = 0.f;

    const int arow  = wm*32 + (lane & 15);
    const int acolh = (lane >> 4) * 16;
    const int brow  = wn*64 + (lane & 7) + ((lane >> 4) << 3);
    const int bcolh = ((lane >> 3) & 1) * 16;

    for (int c = 0; c < 16; c++){
        CP_WAIT1();
        __syncthreads();
        int nc = c + 2;
        if (nc < 16){
            uint32_t st = sb + (nc % 3)*STAGE_BYTES;
            load_chunk(Ab, Bbp, nc*128, st, st + 16384, tid);
            CP_COMMIT();
        }
        int buf = c % 3;
        uint32_t stA = sb + buf*STAGE_BYTES;
        uint32_t stB = stA + 16384;
        #pragma unroll
        for (int ks = 0; ks < 4; ks++){
            int kb = ks*32;
            uint32_t af[2][4], bf[4][4];
            #pragma unroll
            for (int mt = 0; mt < 2; mt++){
                int r = arow + mt*16;
                uint32_t col = (uint32_t)(kb + acolh) ^ (uint32_t)((r & 7) << 4);
                ldm_x4(af[mt], stA + r*128 + col);
            }
            #pragma unroll
            for (int nt = 0; nt < 4; nt++){
                int r = brow + nt*16;
                uint32_t col = (uint32_t)(kb + bcolh) ^ (uint32_t)((r & 7) << 4);
                ldm_x4(bf[nt], stB + r*128 + col);
            }
            #pragma unroll
            for (int mt = 0; mt < 2; mt++)
                #pragma unroll
                for (int nt = 0; nt < 4; nt++){
                    mma16816(acc[mt][nt*2],   af[mt], bf[nt]);
                    mma16816(acc[mt][nt*2+1], af[mt], bf[nt] + 2);
                }
        }
    }

    // epilogue: store raw approx cos
    const int r0 = lane >> 2;
    const int cb = (lane & 3) * 2;
    #pragma unroll
    for (int mt = 0; mt < 2; mt++){
        #pragma unroll
        for (int half = 0; half < 2; half++){
            int ml = wm*32 + mt*16 + half*8 + r0;
            if (ml < Mvalid){
                float* dst = actsBase + (size_t)ml*HH + bn0 + wn*64 + cb;
                #pragma unroll
                for (int nt = 0; nt < 8; nt++){
                    float2 o = make_float2(acc[mt][nt][half*2 + 0], acc[mt][nt][half*2 + 1]);
                    *(float2*)(dst + nt*8) = o;
                }
            }
        }
    }
}

// ---------------- 7. transpose dec_v_w [D,H] -> g_wvT [H,D] ----------------
__global__ void k_trans(const float* __restrict__ W, float* __restrict__ WT)
{
    __shared__ float t[32][33];
    int tx = threadIdx.x & 31, ty = threadIdx.x >> 5;
    int h0 = blockIdx.x * 32, d0 = blockIdx.y * 32;
    #pragma unroll
    for (int j = 0; j < 32; j += 8)
        t[ty+j][tx] = W[(size_t)(d0+ty+j)*HH + h0 + tx];
    __syncthreads();
    #pragma unroll
    for (int j = 0; j < 32; j += 8)
        WT[(size_t)(h0+ty+j)*Dd + d0 + tx] = t[tx][ty+j];
}

// ---------------- 8. select: top-6 -> threshold -> register candidates -> exact rescore ----------------
// Single row read. Candidates come from per-thread top-6 (guarded: if a thread's
// 6th-best >= thr it may hide a 7th candidate -> exact full fallback).
constexpr int CANDMAX = 512;
__global__ void k_select(const float* __restrict__ approx,
                         const __nv_bfloat16* __restrict__ Ap,
                         const __nv_bfloat16* __restrict__ Bt, const __nv_bfloat16* __restrict__ Bv,
                         float* __restrict__ out)
{
    extern __shared__ float fb[];            // 64 KB fallback buffer
    __shared__ float s_arow[1024];
    __shared__ int   s_cand[CANDMAX];
    __shared__ unsigned long long s_key[CANDMAX];
    __shared__ unsigned long long red[8];
    __shared__ unsigned long long s_win;
    __shared__ int   s_cnt;
    __shared__ float selv[32];
    __shared__ int   seli[32];

    const int n = blockIdx.x, tid = threadIdx.x;   // 576 blocks, 256 threads
    const int lane = tid & 31, warp = tid >> 5;
    const float* row = approx + (size_t)n*HH;
    float* latrow = (n < Bb) ? out + OFF_LAT_T + (size_t)n*HH
                             : out + OFF_LAT_V + (size_t)(n-Bb)*HH;
    const int ar = (n < Bb) ? n : n + 64;
    const __nv_bfloat16* arow = Ap + (size_t)ar*2048;
    const __nv_bfloat16* Bp = (n < Bb) ? Bt : Bv;

    // zero latent row + combined fp32 A row
    float4 z = make_float4(0.f, 0.f, 0.f, 0.f);
    for (int i = tid; i < HH/4; i += 256) ((float4*)latrow)[i] = z;
    for (int i = tid; i < 1024; i += 256)
        s_arow[i] = __bfloat162float(arow[i]) + __bfloat162float(arow[1024 + i]);
    if (tid == 0) s_cnt = 0;

    // ---- single pass: per-thread top-6 over the approx row ----
    unsigned long long loc[6] = {0ull,0ull,0ull,0ull,0ull,0ull};
    for (int i = tid; i < HH; i += 256){
        unsigned long long pk = ((unsigned long long)fmap(row[i]) << 32) | (unsigned int)(HH-1-i);
        if (pk > loc[5]){
            loc[5] = pk;
            #pragma unroll
            for (int j = 5; j > 0; j--){
                if (loc[j] > loc[j-1]){ unsigned long long t = loc[j]; loc[j] = loc[j-1]; loc[j-1] = t; }
            }
        }
    }
    unsigned long long locOrig[6];
    #pragma unroll
    for (int j = 0; j < 6; j++) locOrig[j] = loc[j];

    // ---- 32 select rounds to find approx rank-32 ----
    for (int p = 0; p < 32; p++){
        unsigned long long best = loc[0];
        #pragma unroll
        for (int j = 1; j < 6; j++) best = (loc[j] > best) ? loc[j] : best;
        #pragma unroll
        for (int off = 16; off; off >>= 1){
            unsigned long long o = __shfl_down_sync(0xffffffffu, best, off);
            best = (o > best) ? o : best;
        }
        if (lane == 0) red[warp] = best;
        __syncthreads();
        if (tid < 32){
            unsigned long long b2 = (tid < 8) ? red[tid] : 0ull;
            #pragma unroll
            for (int off = 4; off; off >>= 1){
                unsigned long long o = __shfl_down_sync(0xffffffffu, b2, off);
                b2 = (o > b2) ? o : b2;
            }
            if (tid == 0) s_win = b2;
        }
        __syncthreads();
        unsigned long long wk = s_win;
        #pragma unroll
        for (int j = 0; j < 6; j++) if (loc[j] == wk) loc[j] = 0ull;
    }
    const float thr = funmap((unsigned int)(s_win >> 32)) - THR_2DELTA;
    __syncthreads();

    // ---- candidates straight from register top-6 (no second row read) ----
    int myBad = (funmap((unsigned int)(locOrig[5] >> 32)) >= thr) ? 1 : 0;
    #pragma unroll
    for (int j = 0; j < 6; j++){
        if (funmap((unsigned int)(locOrig[j] >> 32)) >= thr){
            int idx = atomicAdd(&s_cnt, 1);
            if (idx < CANDMAX) s_cand[idx] = HH - 1 - (int)(unsigned int)(locOrig[j] & 0xffffffffull);
        }
    }
    int anyBad = __syncthreads_or(myBad);
    int cnt = s_cnt;

    if (!anyBad && cnt <= CANDMAX){
        // ---- exact rescore: warp per candidate ----
        for (int c = warp; c < cnt; c += 8){
            int h = s_cand[c];
            const __nv_bfloat16* br = Bp + (size_t)h*2048;
            float d = 0.f;
            for (int i = lane; i < 1024; i += 32)
                d += s_arow[i] * (__bfloat162float(br[i]) + __bfloat162float(br[1024 + i]));
            #pragma unroll
            for (int off = 16; off; off >>= 1) d += __shfl_xor_sync(0xffffffffu, d, off);
            if (lane == 0){
                float a = acts_of_cos(d);
                s_key[c] = ((unsigned long long)__float_as_uint(a) << 32) | (unsigned int)(HH-1-h);
            }
        }
        __syncthreads();
        // ---- exact top-32 over candidates ----
        for (int p = 0; p < 32; p++){
            unsigned long long best = 0ull;
            for (int c = tid; c < cnt; c += 256) best = (s_key[c] > best) ? s_key[c] : best;
            #pragma unroll
            for (int off = 16; off; off >>= 1){
                unsigned long long o = __shfl_down_sync(0xffffffffu, best, off);
                best = (o > best) ? o : best;
            }
            if (lane == 0) red[warp] = best;
            __syncthreads();
            if (tid < 32){
                unsigned long long b2 = (tid < 8) ? red[tid] : 0ull;
                #pragma unroll
                for (int off = 4; off; off >>= 1){
                    unsigned long long o = __shfl_down_sync(0xffffffffu, b2, off);
                    b2 = (o > b2) ? o : b2;
                }
                if (tid == 0){
                    selv[p] = __uint_as_float((unsigned int)(b2 >> 32));
                    seli[p] = HH - 1 - (int)(unsigned int)(b2 & 0xffffffffull);
                    s_win = b2;
                }
            }
            __syncthreads();
            unsigned long long wk = s_win;
            for (int c = tid; c < cnt; c += 256) if (s_key[c] == wk) s_key[c] = 0ull;
            __syncthreads();
        }
    } else {
        // ---- exact fallback: rescore ALL h (never expected) ----
        for (int h = warp; h < HH; h += 8){
            const __nv_bfloat16* br = Bp + (size_t)h*2048;
            float d = 0.f;
            for (int i = lane; i < 1024; i += 32)
                d += s_arow[i] * (__bfloat162float(br[i]) + __bfloat162float(br[1024 + i]));
            #pragma unroll
            for (int off = 16; off; off >>= 1) d += __shfl_xor_sync(0xffffffffu, d, off);
            if (lane == 0) fb[h] = acts_of_cos(d);
        }
        __syncthreads();
        for (int p = 0; p < 32; p++){
            unsigned long long best = 0ull;
            for (int i = tid; i < HH; i += 256){
                unsigned long long pk = ((unsigned long long)__float_as_uint(fb[i]) << 32) | (unsigned int)(HH-1-i);
                best = (pk > best) ? pk : best;
            }
            #pragma unroll
            for (int off = 16; off; off >>= 1){
                unsigned long long o = __shfl_down_sync(0xffffffffu, best, off);
                best = (o > best) ? o : best;
            }
            if (lane == 0) red[warp] = best;
            __syncthreads();
            if (tid < 32){
                unsigned long long b2 = (tid < 8) ? red[tid] : 0ull;
                #pragma unroll
                for (int off = 4; off; off >>= 1){
                    unsigned long long o = __shfl_down_sync(0xffffffffu, b2, off);
                    b2 = (o > b2) ? o : b2;
                }
                if (tid == 0){
                    int idx = HH - 1 - (int)(unsigned int)(b2 & 0xffffffffull);
                    selv[p] = __uint_as_float((unsigned int)(b2 >> 32));
                    seli[p] = idx;
                    fb[idx] = 0.0f;
                }
            }
            __syncthreads();
        }
    }

    if (tid < 32){
        float v = selv[tid]; int h = seli[tid];
        latrow[h] = v;
        g_tkv[n*32 + tid] = v;
        g_tki[n*32 + tid] = h;
    }
}

// ---------------- 9. sparse reconstruction ----------------
__global__ void k_recon(const float* __restrict__ dec_t_w, const float* __restrict__ dec_t_b,
                        const float* __restrict__ dec_v_b, const float* __restrict__ wvT,
                        float* __restrict__ out)
{
    int n = blockIdx.x, tid = threadIdx.x;
    __shared__ float vk[32];
    __shared__ int   hk[32];
    if (tid < 32){ vk[tid] = g_tkv[n*32+tid]; hk[tid] = g_tki[n*32+tid]; }
    __syncthreads();

    if (n < Bb){
        float* dst = out + OFF_RECON_T + (size_t)n*Dd;
        for (int d = tid; d < Dd; d += 256){
            float acc = dec_t_b[d];
            const float* wr = dec_t_w + (size_t)d*HH;
            #pragma unroll
            for (int k = 0; k < 32; k++) acc += vk[k] * wr[hk[k]];
            dst[d] = acc;
        }
    } else {
        float* dst = out + OFF_RECON_V + (size_t)(n-Bb)*Dd;
        float4 acc = ((const float4*)dec_v_b)[tid];
        #pragma unroll
        for (int k = 0; k < 32; k++){
            float4 wv = ((const float4*)(wvT + (size_t)hk[k]*Dd))[tid];
            float v = vk[k];
            acc.x += v*wv.x; acc.y += v*wv.y; acc.z += v*wv.z; acc.w += v*wv.w;
        }
        ((float4*)dst)[tid] = acc;
    }
}

// ---------------- launch ----------------
extern "C" void kernel_launch(void* const* d_in, const int* in_sizes, int n_in,
                              void* d_out, int out_size)
{
    const float* v_pad    = (const float*)d_in[0];
    const int*   grid_thws= (const int*)  d_in[2];
    const float* t_pad    = (const float*)d_in[3];
    const float* t_mask   = (const float*)d_in[4];
    const float* centers  = (const float*)d_in[5];
    const float* enc_v    = (const float*)d_in[6];
    const float* dec_v_w  = (const float*)d_in[7];
    const float* dec_v_b  = (const float*)d_in[8];
    const float* enc_t    = (const float*)d_in[9];
    const float* dec_t_w  = (const float*)d_in[10];
    const float* dec_t_b  = (const float*)d_in[11];
    float* out = (float*)d_out;

    float *p_acts, *p_wvT;
    __nv_bfloat16 *p_apack, *p_bt, *p_bv;
    cudaGetSymbolAddress((void**)&p_acts,  g_acts);
    cudaGetSymbolAddress((void**)&p_wvT,   g_wvT);
    cudaGetSymbolAddress((void**)&p_apack, g_apack);
    cudaGetSymbolAddress((void**)&p_bt,    g_bt);
    cudaGetSymbolAddress((void**)&p_bv,    g_bv);

    cudaFuncSetAttribute(k_views,    cudaFuncAttributeMaxDynamicSharedMemorySize, 65536);
    cudaFuncSetAttribute(k_gemm_mma, cudaFuncAttributeMaxDynamicSharedMemorySize, GEMM_SMEM);
    cudaFuncSetAttribute(k_select,   cudaFuncAttributeMaxDynamicSharedMemorySize, 65536);

    k_tglobal<<<Bb*4, 256>>>(t_pad, t_mask, out);
    k_mden<<<Bb, 256>>>(centers, grid_thws);
    k_views<<<Bb*4, 128, 65536>>>(v_pad, out);
    k_packb<<<dim3(HH/8, 2), 256>>>(enc_t, enc_v, p_bt, p_bv);
    k_packa<<<640, 256>>>(out, p_apack);
    k_gemm_mma<<<dim3(HH/128, 5), 256, GEMM_SMEM>>>(p_apack, p_bt, p_bv, p_acts);
    k_trans<<<dim3(HH/32, Dd/32), 256>>>(dec_v_w, p_wvT);
    k_select<<<NROW, 256, 65536>>>(p_acts, p_apack, p_bt, p_bv, out);
    k_recon<<<NROW, 256>>>(dec_t_w, dec_t_b, dec_v_b, p_wvT, out);
}

// round 17
// speedup vs baseline: 1.3824x; 1.0212x over previous
#include <cuda_runtime.h>
#include <cuda_bf16.h>
#include <cstdint>

// ---------------- problem constants ----------------
constexpr int   Bb   = 64;
constexpr int   Dd   = 1024;
constexpr int   Tt   = 512;
constexpr int   KC   = 8;
constexpr int   HH   = 16384;
constexpr int   LMAX = 1024;
constexpr int   NROW = Bb + Bb*KC;   // 576
constexpr float GAMMA_C   = 10.0f;
constexpr float EPS_POOL  = 1e-6f;
constexpr float EPS_NORM  = 1e-12f;
constexpr float THR_2DELTA = 0.0025f;  // ~19-sigma combined vs 1.3e-4 RMS hi-only error

// output layout (floats)
constexpr size_t OFF_RECON_V = 0;
constexpr size_t OFF_VIEWS   = OFF_RECON_V + (size_t)Bb*KC*Dd;
constexpr size_t OFF_RECON_T = OFF_VIEWS   + (size_t)Bb*KC*Dd;
constexpr size_t OFF_TGLOBAL = OFF_RECON_T + (size_t)Bb*Dd;
constexpr size_t OFF_LAT_V   = OFF_TGLOBAL + (size_t)Bb*Dd;
constexpr size_t OFF_LAT_T   = OFF_LAT_V   + (size_t)Bb*KC*HH;
constexpr size_t OUT_TOTAL   = OFF_LAT_T   + (size_t)Bb*HH;

// ---------------- scratch ----------------
__device__ float g_acts[(size_t)NROW*HH];               // approx cos, 36 MB
__device__ float g_m[(size_t)Bb*KC*LMAX];
__device__ float g_den[Bb*KC];
__device__ float g_tkv[NROW*32];
__device__ int   g_tki[NROW*32];
__device__ float g_wvT[(size_t)HH*Dd];                  // 64 MB transposed dec_v_w
__device__ __nv_bfloat16 g_apack[(size_t)640*2048];     // [hiX, loX] (xinv folded)
__device__ __nv_bfloat16 g_bt[(size_t)HH*2048];         // [hiW, loW] text (winv folded)
__device__ __nv_bfloat16 g_bv[(size_t)HH*2048];         // [hiW, loW] views (winv folded)

// ---------------- PTX helpers ----------------
__device__ __forceinline__ uint32_t smem_u32(const void* p){
    uint32_t a; asm("{ .reg .u64 t; cvta.to.shared.u64 t, %1; cvt.u32.u64 %0, t; }" : "=r"(a) : "l"(p));
    return a;
}
__device__ __forceinline__ void fma2(unsigned long long &c, unsigned long long a, unsigned long long b){
    asm("fma.rn.f32x2 %0, %1, %2, %0;" : "+l"(c) : "l"(a), "l"(b));
}
__device__ __forceinline__ unsigned long long dup2(float x){
    unsigned long long r; asm("mov.b64 %0, {%1, %1};" : "=l"(r) : "f"(x)); return r;
}
__device__ __forceinline__ float2 unpk(unsigned long long v){
    float2 r; asm("mov.b64 {%0, %1}, %2;" : "=f"(r.x), "=f"(r.y) : "l"(v)); return r;
}
__device__ __forceinline__ void cp_async16(uint32_t s, const void* g){
    asm volatile("cp.async.cg.shared.global [%0], [%1], 16;" :: "r"(s), "l"(g));
}
#define CP_COMMIT() asm volatile("cp.async.commit_group;" ::: "memory")
#define CP_WAIT1()  asm volatile("cp.async.wait_group 1;" ::: "memory")

__device__ __forceinline__ void ldm_x4(uint32_t* r, uint32_t addr){
    asm volatile("ldmatrix.sync.aligned.m8n8.x4.shared.b16 {%0,%1,%2,%3}, [%4];"
        : "=r"(r[0]), "=r"(r[1]), "=r"(r[2]), "=r"(r[3]) : "r"(addr));
}
__device__ __forceinline__ void mma16816(float* c, const uint32_t* a, const uint32_t* b){
    asm volatile("mma.sync.aligned.m16n8k16.row.col.f32.bf16.bf16.f32 "
        "{%0,%1,%2,%3}, {%4,%5,%6,%7}, {%8,%9}, {%0,%1,%2,%3};"
        : "+f"(c[0]), "+f"(c[1]), "+f"(c[2]), "+f"(c[3])
        : "r"(a[0]), "r"(a[1]), "r"(a[2]), "r"(a[3]), "r"(b[0]), "r"(b[1]));
}
// order-preserving map for float bits (handles negatives)
__device__ __forceinline__ unsigned int fmap(float f){
    unsigned int b = __float_as_uint(f);
    return b ^ (((int)b >> 31) | 0x80000000u);
}
__device__ __forceinline__ float funmap(unsigned int m){
    unsigned int rb = (m & 0x80000000u) ? (m ^ 0x80000000u) : ~m;
    return __uint_as_float(rb);
}
__device__ __forceinline__ float acts_of_cos(float c){
    float cc = fminf(1.f, fmaxf(-1.f, c));
    return 2.f - sqrtf(fmaxf(0.f, 2.f - 2.f*cc));
}
// dot of combined fp32 smem row with [hi|lo] bf16 gmem row, warp-parallel, vectorized
__device__ __forceinline__ float warp_dot(const float* s_arow, const __nv_bfloat16* br, int lane){
    const unsigned long long* hp = (const unsigned long long*)br;          // 256 ulls
    const unsigned long long* lp = (const unsigned long long*)(br + 1024); // 256 ulls
    const float4* sp = (const float4*)s_arow;                              // 256 float4
    float d = 0.f;
    #pragma unroll
    for (int j = lane; j < 256; j += 32){
        union { unsigned long long u; __nv_bfloat16 b[4]; } h, l;
        h.u = hp[j]; l.u = lp[j];
        float4 sa = sp[j];
        d += sa.x * (__bfloat162float(h.b[0]) + __bfloat162float(l.b[0]));
        d += sa.y * (__bfloat162float(h.b[1]) + __bfloat162float(l.b[1]));
        d += sa.z * (__bfloat162float(h.b[2]) + __bfloat162float(l.b[2]));
        d += sa.w * (__bfloat162float(h.b[3]) + __bfloat162float(l.b[3]));
    }
    #pragma unroll
    for (int off = 16; off; off >>= 1) d += __shfl_xor_sync(0xffffffffu, d, off);
    return d;
}

// ---------------- 1. text global pooling ----------------
__global__ void k_tglobal(const float* __restrict__ t_pad, const float* __restrict__ t_mask,
                          float* __restrict__ out)
{
    int blk = blockIdx.x;
    int b = blk >> 2, ch = blk & 3;
    int tid = threadIdx.x;
    __shared__ float sm[Tt];
    __shared__ float s_inv;
    for (int t = tid; t < Tt; t += 256) sm[t] = t_mask[b*Tt + t];
    __syncthreads();
    if (tid == 0){
        float s = 0.f;
        for (int t = 0; t < Tt; t++) s += sm[t];
        s_inv = 1.f / (s + EPS_POOL);
    }
    __syncthreads();
    int d0 = ch*256 + tid;
    const float* tp = t_pad + (size_t)b*Tt*Dd + d0;
    float acc = 0.f;
    #pragma unroll 4
    for (int t = 0; t < Tt; t++) acc += tp[(size_t)t*Dd] * sm[t];
    out[OFF_TGLOBAL + (size_t)b*Dd + d0] = acc * s_inv;
}

// ---------------- 2. gaussian weights ----------------
__global__ void k_mden(const float* __restrict__ centers, const int* __restrict__ grid_thws)
{
    int b = blockIdx.x, tid = threadIdx.x;
    int Hg = grid_thws[1], Wg = grid_thws[2];
    int L  = Hg * Wg;
    __shared__ float partial[KC][8];
    int lane = tid & 31, warp = tid >> 5;
    for (int k = 0; k < KC; k++){
        float cx = centers[(b*KC+k)*2 + 0];
        float cy = centers[(b*KC+k)*2 + 1];
        float local = 0.f;
        for (int l = tid; l < L; l += 256){
            int iy = l / Wg, ix = l % Wg;
            float px = (ix + 0.5f) / (float)Wg;
            float py = (iy + 0.5f) / (float)Hg;
            float dx = cx - px, dy = cy - py;
            float m = expf(-GAMMA_C * (dx*dx + dy*dy));
            g_m[((size_t)b*KC + k)*LMAX + l] = m;
            local += m;
        }
        #pragma unroll
        for (int off = 16; off; off >>= 1) local += __shfl_down_sync(0xffffffffu, local, off);
        if (lane == 0) partial[k][warp] = local;
    }
    __syncthreads();
    if (tid < KC){
        float s = 0.f;
        #pragma unroll
        for (int w = 0; w < 8; w++) s += partial[tid][w];
        g_den[b*KC + tid] = s;
    }
}

// ---------------- 3. gaussian view pooling (f32x2) ----------------
__global__ void k_views(const float* __restrict__ v_pad, float* __restrict__ out)
{
    extern __shared__ unsigned long long ms2[];
    int blk = blockIdx.x;
    int b = blk >> 2, ch = blk & 3;
    int tid = threadIdx.x;               // 128
    for (int i = tid; i < KC*LMAX; i += 128) ms2[i] = dup2(g_m[(size_t)b*KC*LMAX + i]);
    __syncthreads();

    int d0 = ch*256 + tid*2;
    const float* vp = v_pad + (size_t)b*LMAX*Dd + d0;
    unsigned long long acc[KC];
    #pragma unroll
    for (int k = 0; k < KC; k++) acc[k] = 0ull;

    for (int l = 0; l < LMAX; l++){
        unsigned long long v = *(const unsigned long long*)(vp + (size_t)l*Dd);
        #pragma unroll
        for (int k = 0; k < KC; k++) fma2(acc[k], ms2[k*LMAX + l], v);
    }
    #pragma unroll
    for (int k = 0; k < KC; k++){
        float inv = 1.f / (g_den[b*KC + k] + EPS_POOL);
        float2 a = unpk(acc[k]);
        float2 o = make_float2(a.x*inv, a.y*inv);
        *(float2*)(out + OFF_VIEWS + ((size_t)(b*KC + k))*Dd + d0) = o;
    }
}

// ---------------- 4. pack B (both enc matrices): warp-per-row, winv folded ----------------
__global__ void k_packb(const float* __restrict__ enc_t, const float* __restrict__ enc_v,
                        __nv_bfloat16* __restrict__ bt, __nv_bfloat16* __restrict__ bv)
{
    const float* enc = blockIdx.y ? enc_v : enc_t;
    __nv_bfloat16* Bp = blockIdx.y ? bv : bt;
    int warp = threadIdx.x >> 5, lane = threadIdx.x & 31;
    int n = blockIdx.x*8 + warp;

    const float4* src = (const float4*)(enc + (size_t)n*Dd);
    float4 v[8];
    float s = 0.f;
    #pragma unroll
    for (int i = 0; i < 8; i++){
        v[i] = src[i*32 + lane];
        s += v[i].x*v[i].x + v[i].y*v[i].y + v[i].z*v[i].z + v[i].w*v[i].w;
    }
    #pragma unroll
    for (int off = 16; off; off >>= 1) s += __shfl_xor_sync(0xffffffffu, s, off);
    float sc = 1.f / fmaxf(sqrtf(s), EPS_NORM);

    __nv_bfloat16* row = Bp + (size_t)n*2048;
    #pragma unroll
    for (int i = 0; i < 8; i++){
        float xs[4] = {v[i].x*sc, v[i].y*sc, v[i].z*sc, v[i].w*sc};
        union { __nv_bfloat16 b[4]; unsigned long long u; } uh, ul;
        #pragma unroll
        for (int j = 0; j < 4; j++){
            __nv_bfloat16 h = __float2bfloat16(xs[j]);
            uh.b[j] = h;
            ul.b[j] = __float2bfloat16(xs[j] - __bfloat162float(h));
        }
        int e = (i*32 + lane)*4;
        *(unsigned long long*)(row + e)        = uh.u;
        *(unsigned long long*)(row + 1024 + e) = ul.u;
    }
}

// ---------------- 5. pack A [hi, lo] with fused row norm (rows 64..127 pad zeros) ----------------
__global__ void k_packa(const float* __restrict__ out, __nv_bfloat16* __restrict__ Ap)
{
    int r = blockIdx.x, tid = threadIdx.x;     // 640 blocks, 256 threads
    float4 v = make_float4(0.f, 0.f, 0.f, 0.f);
    if (r < 64)        v = ((const float4*)(out + OFF_TGLOBAL + (size_t)r*Dd))[tid];
    else if (r >= 128) v = ((const float4*)(out + OFF_VIEWS + (size_t)(r-128)*Dd))[tid];

    float s = v.x*v.x + v.y*v.y + v.z*v.z + v.w*v.w;
    __shared__ float ws[8];
    __shared__ float s_scale;
    int lane = tid & 31, warp = tid >> 5;
    #pragma unroll
    for (int off = 16; off; off >>= 1) s += __shfl_down_sync(0xffffffffu, s, off);
    if (lane == 0) ws[warp] = s;
    __syncthreads();
    if (tid == 0){
        float t = 0.f;
        #pragma unroll
        for (int w = 0; w < 8; w++) t += ws[w];
        s_scale = 1.f / fmaxf(sqrtf(t), EPS_NORM);
    }
    __syncthreads();
    float sc = s_scale;

    float xs[4] = {v.x*sc, v.y*sc, v.z*sc, v.w*sc};
    union { __nv_bfloat16 b[4]; unsigned long long u; } uh, ul;
    #pragma unroll
    for (int i = 0; i < 4; i++){
        __nv_bfloat16 h = __float2bfloat16(xs[i]);
        uh.b[i] = h;
        ul.b[i] = __float2bfloat16(xs[i] - __bfloat162float(h));
    }
    __nv_bfloat16* row = Ap + (size_t)r*2048;
    *(unsigned long long*)(row + tid*4)        = uh.u;
    *(unsigned long long*)(row + 1024 + tid*4) = ul.u;
}

// ---------------- 6. hi-only bf16 GEMM (approx cos), R8 mainloop config ----------------
constexpr int STAGE_BYTES = 32768;                 // A 16KB + B 16KB
constexpr int GEMM_SMEM   = 1024 + 3*STAGE_BYTES;  // ~97 KB

__device__ __forceinline__ void load_chunk(const char* Ab, const char* Bbp, int off,
                                           uint32_t smA, uint32_t smB, int tid)
{
    #pragma unroll
    for (int i = 0; i < 4; i++){            // A: 128 rows x 8 segs (hi region)
        int idx = i*256 + tid;
        int row = idx >> 3, seg = idx & 7;
        uint32_t col = (uint32_t)(seg*16) ^ (uint32_t)((row & 7) << 4);
        cp_async16(smA + row*128 + col, Ab + (size_t)row*4096 + off + seg*16);
    }
    #pragma unroll
    for (int i = 0; i < 4; i++){            // B: 128 rows x 8 segs (hi region)
        int idx = i*256 + tid;
        int row = idx >> 3, seg = idx & 7;
        uint32_t col = (uint32_t)(seg*16) ^ (uint32_t)((row & 7) << 4);
        cp_async16(smB + row*128 + col, Bbp + (size_t)row*4096 + off + seg*16);
    }
}

__global__ void __launch_bounds__(256, 2)
k_gemm_mma(const __nv_bfloat16* __restrict__ Apack,
           const __nv_bfloat16* __restrict__ Bt, const __nv_bfloat16* __restrict__ Bv,
           float* __restrict__ acts)
{
    extern __shared__ char dsm[];
    const int tid = threadIdx.x;
    const int by  = blockIdx.y;
    const int bn0 = blockIdx.x * 128;
    const int Mvalid = by ? 128 : 64;
    const __nv_bfloat16* Bpack = by ? Bv : Bt;
    float* actsBase = acts + (by ? (size_t)(64 + (by-1)*128)*HH : 0);

    uint32_t sb = (smem_u32(dsm) + 1023u) & ~1023u;
    const char* Ab  = (const char*)(Apack + (size_t)by*128*2048);
    const char* Bbp = (const char*)(Bpack + (size_t)bn0*2048);

    #pragma unroll
    for (int c = 0; c < 2; c++){
        uint32_t st = sb + c*STAGE_BYTES;
        load_chunk(Ab, Bbp, c*128, st, st + 16384, tid);
        CP_COMMIT();
    }

    const int w = tid >> 5, lane = tid & 31;
    const int wm = w & 3, wn = w >> 2;

    float acc[2][8][4];
    #pragma unroll
    for (int mt = 0; mt < 2; mt++)
        #pragma unroll
        for (int nt = 0; nt < 8; nt++)
            #pragma unroll
            for (int j = 0; j < 4; j++) acc[mt][nt][j] = 0.f;

    const int arow  = wm*32 + (lane & 15);
    const int acolh = (lane >> 4) * 16;
    const int brow  = wn*64 + (lane & 7) + ((lane >> 4) << 3);
    const int bcolh = ((lane >> 3) & 1) * 16;

    for (int c = 0; c < 16; c++){
        CP_WAIT1();
        __syncthreads();
        int nc = c + 2;
        if (nc < 16){
            uint32_t st = sb + (nc % 3)*STAGE_BYTES;
            load_chunk(Ab, Bbp, nc*128, st, st + 16384, tid);
            CP_COMMIT();
        }
        int buf = c % 3;
        uint32_t stA = sb + buf*STAGE_BYTES;
        uint32_t stB = stA + 16384;
        #pragma unroll
        for (int ks = 0; ks < 4; ks++){
            int kb = ks*32;
            uint32_t af[2][4], bf[4][4];
            #pragma unroll
            for (int mt = 0; mt < 2; mt++){
                int r = arow + mt*16;
                uint32_t col = (uint32_t)(kb + acolh) ^ (uint32_t)((r & 7) << 4);
                ldm_x4(af[mt], stA + r*128 + col);
            }
            #pragma unroll
            for (int nt = 0; nt < 4; nt++){
                int r = brow + nt*16;
                uint32_t col = (uint32_t)(kb + bcolh) ^ (uint32_t)((r & 7) << 4);
                ldm_x4(bf[nt], stB + r*128 + col);
            }
            #pragma unroll
            for (int mt = 0; mt < 2; mt++)
                #pragma unroll
                for (int nt = 0; nt < 4; nt++){
                    mma16816(acc[mt][nt*2],   af[mt], bf[nt]);
                    mma16816(acc[mt][nt*2+1], af[mt], bf[nt] + 2);
                }
        }
    }

    // epilogue: store raw approx cos
    const int r0 = lane >> 2;
    const int cb = (lane & 3) * 2;
    #pragma unroll
    for (int mt = 0; mt < 2; mt++){
        #pragma unroll
        for (int half = 0; half < 2; half++){
            int ml = wm*32 + mt*16 + half*8 + r0;
            if (ml < Mvalid){
                float* dst = actsBase + (size_t)ml*HH + bn0 + wn*64 + cb;
                #pragma unroll
                for (int nt = 0; nt < 8; nt++){
                    float2 o = make_float2(acc[mt][nt][half*2 + 0], acc[mt][nt][half*2 + 1]);
                    *(float2*)(dst + nt*8) = o;
                }
            }
        }
    }
}

// ---------------- 7. transpose dec_v_w [D,H] -> g_wvT [H,D] ----------------
__global__ void k_trans(const float* __restrict__ W, float* __restrict__ WT)
{
    __shared__ float t[32][33];
    int tx = threadIdx.x & 31, ty = threadIdx.x >> 5;
    int h0 = blockIdx.x * 32, d0 = blockIdx.y * 32;
    #pragma unroll
    for (int j = 0; j < 32; j += 8)
        t[ty+j][tx] = W[(size_t)(d0+ty+j)*HH + h0 + tx];
    __syncthreads();
    #pragma unroll
    for (int j = 0; j < 32; j += 8)
        WT[(size_t)(h0+ty+j)*Dd + d0 + tx] = t[tx][ty+j];
}

// ---------------- 8. select: top-6 -> threshold -> register candidates -> exact rescore ----------------
constexpr int CANDMAX = 512;
__global__ void k_select(const float* __restrict__ approx,
                         const __nv_bfloat16* __restrict__ Ap,
                         const __nv_bfloat16* __restrict__ Bt, const __nv_bfloat16* __restrict__ Bv,
                         float* __restrict__ out)
{
    extern __shared__ float fb[];            // 64 KB fallback buffer
    __shared__ float s_arow[1024];
    __shared__ int   s_cand[CANDMAX];
    __shared__ unsigned long long s_key[CANDMAX];
    __shared__ unsigned long long red[8];
    __shared__ unsigned long long s_win;
    __shared__ int   s_cnt;
    __shared__ float selv[32];
    __shared__ int   seli[32];

    const int n = blockIdx.x, tid = threadIdx.x;   // 576 blocks, 256 threads
    const int lane = tid & 31, warp = tid >> 5;
    const float* row = approx + (size_t)n*HH;
    float* latrow = (n < Bb) ? out + OFF_LAT_T + (size_t)n*HH
                             : out + OFF_LAT_V + (size_t)(n-Bb)*HH;
    const int ar = (n < Bb) ? n : n + 64;
    const __nv_bfloat16* arow = Ap + (size_t)ar*2048;
    const __nv_bfloat16* Bp = (n < Bb) ? Bt : Bv;

    // zero latent row + combined fp32 A row
    float4 z = make_float4(0.f, 0.f, 0.f, 0.f);
    for (int i = tid; i < HH/4; i += 256) ((float4*)latrow)[i] = z;
    for (int i = tid; i < 1024; i += 256)
        s_arow[i] = __bfloat162float(arow[i]) + __bfloat162float(arow[1024 + i]);
    if (tid == 0) s_cnt = 0;

    // ---- single pass: per-thread top-6 over the approx row ----
    unsigned long long loc[6] = {0ull,0ull,0ull,0ull,0ull,0ull};
    for (int i = tid; i < HH; i += 256){
        unsigned long long pk = ((unsigned long long)fmap(row[i]) << 32) | (unsigned int)(HH-1-i);
        if (pk > loc[5]){
            loc[5] = pk;
            #pragma unroll
            for (int j = 5; j > 0; j--){
                if (loc[j] > loc[j-1]){ unsigned long long t = loc[j]; loc[j] = loc[j-1]; loc[j-1] = t; }
            }
        }
    }
    unsigned long long locOrig[6];
    #pragma unroll
    for (int j = 0; j < 6; j++) locOrig[j] = loc[j];

    // ---- 32 select rounds to find approx rank-32 ----
    for (int p = 0; p < 32; p++){
        unsigned long long best = loc[0];
        #pragma unroll
        for (int j = 1; j < 6; j++) best = (loc[j] > best) ? loc[j] : best;
        #pragma unroll
        for (int off = 16; off; off >>= 1){
            unsigned long long o = __shfl_down_sync(0xffffffffu, best, off);
            best = (o > best) ? o : best;
        }
        if (lane == 0) red[warp] = best;
        __syncthreads();
        if (tid < 32){
            unsigned long long b2 = (tid < 8) ? red[tid] : 0ull;
            #pragma unroll
            for (int off = 4; off; off >>= 1){
                unsigned long long o = __shfl_down_sync(0xffffffffu, b2, off);
                b2 = (o > b2) ? o : b2;
            }
            if (tid == 0) s_win = b2;
        }
        __syncthreads();
        unsigned long long wk = s_win;
        #pragma unroll
        for (int j = 0; j < 6; j++) if (loc[j] == wk) loc[j] = 0ull;
    }
    const float thr = funmap((unsigned int)(s_win >> 32)) - THR_2DELTA;
    __syncthreads();

    // ---- candidates straight from register top-6 ----
    int myBad = (funmap((unsigned int)(locOrig[5] >> 32)) >= thr) ? 1 : 0;
    #pragma unroll
    for (int j = 0; j < 6; j++){
        if (funmap((unsigned int)(locOrig[j] >> 32)) >= thr){
            int idx = atomicAdd(&s_cnt, 1);
            if (idx < CANDMAX) s_cand[idx] = HH - 1 - (int)(unsigned int)(locOrig[j] & 0xffffffffull);
        }
    }
    int anyBad = __syncthreads_or(myBad);
    int cnt = s_cnt;

    if (!anyBad && cnt <= CANDMAX){
        // ---- exact rescore: warp per candidate (vectorized) ----
        for (int c = warp; c < cnt; c += 8){
            int h = s_cand[c];
            float d = warp_dot(s_arow, Bp + (size_t)h*2048, lane);
            if (lane == 0){
                float a = acts_of_cos(d);
                s_key[c] = ((unsigned long long)__float_as_uint(a) << 32) | (unsigned int)(HH-1-h);
            }
        }
        __syncthreads();
        // ---- exact top-32 over candidates ----
        for (int p = 0; p < 32; p++){
            unsigned long long best = 0ull;
            for (int c = tid; c < cnt; c += 256) best = (s_key[c] > best) ? s_key[c] : best;
            #pragma unroll
            for (int off = 16; off; off >>= 1){
                unsigned long long o = __shfl_down_sync(0xffffffffu, best, off);
                best = (o > best) ? o : best;
            }
            if (lane == 0) red[warp] = best;
            __syncthreads();
            if (tid < 32){
                unsigned long long b2 = (tid < 8) ? red[tid] : 0ull;
                #pragma unroll
                for (int off = 4; off; off >>= 1){
                    unsigned long long o = __shfl_down_sync(0xffffffffu, b2, off);
                    b2 = (o > b2) ? o : b2;
                }
                if (tid == 0){
                    selv[p] = __uint_as_float((unsigned int)(b2 >> 32));
                    seli[p] = HH - 1 - (int)(unsigned int)(b2 & 0xffffffffull);
                    s_win = b2;
                }
            }
            __syncthreads();
            unsigned long long wk = s_win;
            for (int c = tid; c < cnt; c += 256) if (s_key[c] == wk) s_key[c] = 0ull;
            __syncthreads();
        }
    } else {
        // ---- exact fallback: rescore ALL h (never expected) ----
        for (int h = warp; h < HH; h += 8){
            float d = warp_dot(s_arow, Bp + (size_t)h*2048, lane);
            if (lane == 0) fb[h] = acts_of_cos(d);
        }
        __syncthreads();
        for (int p = 0; p < 32; p++){
            unsigned long long best = 0ull;
            for (int i = tid; i < HH; i += 256){
                unsigned long long pk = ((unsigned long long)__float_as_uint(fb[i]) << 32) | (unsigned int)(HH-1-i);
                best = (pk > best) ? pk : best;
            }
            #pragma unroll
            for (int off = 16; off; off >>= 1){
                unsigned long long o = __shfl_down_sync(0xffffffffu, best, off);
                best = (o > best) ? o : best;
            }
            if (lane == 0) red[warp] = best;
            __syncthreads();
            if (tid < 32){
                unsigned long long b2 = (tid < 8) ? red[tid] : 0ull;
                #pragma unroll
                for (int off = 4; off; off >>= 1){
                    unsigned long long o = __shfl_down_sync(0xffffffffu, b2, off);
                    b2 = (o > b2) ? o : b2;
                }
                if (tid == 0){
                    int idx = HH - 1 - (int)(unsigned int)(b2 & 0xffffffffull);
                    selv[p] = __uint_as_float((unsigned int)(b2 >> 32));
                    seli[p] = idx;
                    fb[idx] = 0.0f;
                }
            }
            __syncthreads();
        }
    }

    if (tid < 32){
        float v = selv[tid]; int h = seli[tid];
        latrow[h] = v;
        g_tkv[n*32 + tid] = v;
        g_tki[n*32 + tid] = h;
    }
}

// ---------------- 9. sparse reconstruction ----------------
__global__ void k_recon(const float* __restrict__ dec_t_w, const float* __restrict__ dec_t_b,
                        const float* __restrict__ dec_v_b, const float* __restrict__ wvT,
                        float* __restrict__ out)
{
    int n = blockIdx.x, tid = threadIdx.x;
    __shared__ float vk[32];
    __shared__ int   hk[32];
    if (tid < 32){ vk[tid] = g_tkv[n*32+tid]; hk[tid] = g_tki[n*32+tid]; }
    __syncthreads();

    if (n < Bb){
        float* dst = out + OFF_RECON_T + (size_t)n*Dd;
        for (int d = tid; d < Dd; d += 256){
            float acc = dec_t_b[d];
            const float* wr = dec_t_w + (size_t)d*HH;
            #pragma unroll
            for (int k = 0; k < 32; k++) acc += vk[k] * wr[hk[k]];
            dst[d] = acc;
        }
    } else {
        float* dst = out + OFF_RECON_V + (size_t)(n-Bb)*Dd;
        float4 acc = ((const float4*)dec_v_b)[tid];
        #pragma unroll
        for (int k = 0; k < 32; k++){
            float4 wv = ((const float4*)(wvT + (size_t)hk[k]*Dd))[tid];
            float v = vk[k];
            acc.x += v*wv.x; acc.y += v*wv.y; acc.z += v*wv.z; acc.w += v*wv.w;
        }
        ((float4*)dst)[tid] = acc;
    }
}

// ---------------- launch ----------------
extern "C" void kernel_launch(void* const* d_in, const int* in_sizes, int n_in,
                              void* d_out, int out_size)
{
    const float* v_pad    = (const float*)d_in[0];
    const int*   grid_thws= (const int*)  d_in[2];
    const float* t_pad    = (const float*)d_in[3];
    const float* t_mask   = (const float*)d_in[4];
    const float* centers  = (const float*)d_in[5];
    const float* enc_v    = (const float*)d_in[6];
    const float* dec_v_w  = (const float*)d_in[7];
    const float* dec_v_b  = (const float*)d_in[8];
    const float* enc_t    = (const float*)d_in[9];
    const float* dec_t_w  = (const float*)d_in[10];
    const float* dec_t_b  = (const float*)d_in[11];
    float* out = (float*)d_out;

    float *p_acts, *p_wvT;
    __nv_bfloat16 *p_apack, *p_bt, *p_bv;
    cudaGetSymbolAddress((void**)&p_acts,  g_acts);
    cudaGetSymbolAddress((void**)&p_wvT,   g_wvT);
    cudaGetSymbolAddress((void**)&p_apack, g_apack);
    cudaGetSymbolAddress((void**)&p_bt,    g_bt);
    cudaGetSymbolAddress((void**)&p_bv,    g_bv);

    cudaFuncSetAttribute(k_views,    cudaFuncAttributeMaxDynamicSharedMemorySize, 65536);
    cudaFuncSetAttribute(k_gemm_mma, cudaFuncAttributeMaxDynamicSharedMemorySize, GEMM_SMEM);
    cudaFuncSetAttribute(k_select,   cudaFuncAttributeMaxDynamicSharedMemorySize, 65536);

    k_tglobal<<<Bb*4, 256>>>(t_pad, t_mask, out);
    k_mden<<<Bb, 256>>>(centers, grid_thws);
    k_views<<<Bb*4, 128, 65536>>>(v_pad, out);
    k_packb<<<dim3(HH/8, 2), 256>>>(enc_t, enc_v, p_bt, p_bv);
    k_packa<<<640, 256>>>(out, p_apack);
    k_gemm_mma<<<dim3(HH/128, 5), 256, GEMM_SMEM>>>(p_apack, p_bt, p_bv, p_acts);
    k_trans<<<dim3(HH/32, Dd/32), 256>>>(dec_v_w, p_wvT);
    k_select<<<NROW, 256, 65536>>>(p_acts, p_apack, p_bt, p_bv, out);
    k_recon<<<NROW, 256>>>(dec_t_w, dec_t_b, dec_v_b, p_wvT, out);
}